// round 14
// baseline (speedup 1.0000x reference)
#include <cuda_runtime.h>
#include <cuda_fp16.h>
#include <cstdint>

#define HD 512
#define BT 32768
#define BSZ 128
#define KBM 4096
#define KBTOT 32768

typedef unsigned int u32;
typedef unsigned long long u64;
typedef unsigned short u16;

// weight plane slot offsets (elements)
#define BIG    524288ULL                  // 512n x 1024k
#define SMALL  262144ULL                  // 512n x 512k
#define W1OFF  0ULL                       // 3 BIG: arn1, add1, wc1
#define WKOFF  (3ULL*BIG)                 // 6 SMALL Wk
#define WQOFF  (WKOFF + 6ULL*SMALL)       // 6 SMALL Wq
#define WSOFF2 (WQOFF + 6ULL*SMALL)       // 7 SMALL: arn2,arn3,add2,add3,wc2,wc3,wc4
#define WTOT   (WSOFF2 + 7ULL*SMALL)

#define ATTZ   2097152ULL                 // 4096 x 512 per dim
#define H1S    16777216ULL                // 32768 x 512
#define H1_OFF 33554432ULL
#define H2_OFF (H1_OFF + 3*H1S)

__device__ u16   g_wbh[WTOT];
__device__ u16   g_wbl[WTOT];
__device__ u16   g_atth[3*ATTZ];
__device__ u16   g_qh[65536];
__device__ u16   g_ah[134217728];         // hi planes: info + h1[3] + h2[3] (+h3)
__device__ float g_qb[6*128*512];
__device__ u16   g_arnh[(size_t)BT*HD];
__device__ u16   g_addh[(size_t)BT*HD];
__device__ float g_upart[16*6*KBM];
__device__ float g_eng[BT];
__device__ int   g_maskmode;

__device__ __forceinline__ void split2(float v, u16& h, u16& l) {
    __half hh = __float2half_rn(v);
    h = __half_as_ushort(hh);
    l = __half_as_ushort(__float2half_rn(v - __half2float(hh)));
}
__device__ __forceinline__ u32 cvt2(float v0, float v1) {
    u32 r;
    asm("cvt.rn.f16x2.f32 %0, %1, %2;" : "=r"(r) : "f"(v1), "f"(v0));
    return r;
}
__device__ __forceinline__ u32 smem_u32(const void* p) {
    u32 a;
    asm("{ .reg .u64 t; cvta.to.shared.u64 t, %1; cvt.u32.u64 %0, t; }" : "=r"(a) : "l"(p));
    return a;
}
__device__ __forceinline__ void cp16(u32 dst, const void* src) {
    asm volatile("cp.async.cg.shared.global [%0], [%1], 16;" :: "r"(dst), "l"(src));
}
__device__ __forceinline__ void ldsm4(u32* r, u32 a) {
    asm volatile("ldmatrix.sync.aligned.m8n8.x4.shared.b16 {%0,%1,%2,%3}, [%4];"
                 : "=r"(r[0]), "=r"(r[1]), "=r"(r[2]), "=r"(r[3]) : "r"(a));
}
__device__ __forceinline__ void mma16816(float* c, const u32* a, const u32* b) {
    asm volatile("mma.sync.aligned.m16n8k16.row.col.f32.f16.f16.f32 "
                 "{%0,%1,%2,%3},{%4,%5,%6,%7},{%8,%9},{%0,%1,%2,%3};"
                 : "+f"(c[0]), "+f"(c[1]), "+f"(c[2]), "+f"(c[3])
                 : "r"(a[0]), "r"(a[1]), "r"(a[2]), "r"(a[3]), "r"(b[0]), "r"(b[1]));
}

// ---------------- stage loader: k-tile 64, 128B rows, chunk^(row&7) swizzle --
// A-hi @0 (16KB), B-hi @16384; stage stride 32768; 3 stages; 256 threads.
__device__ __forceinline__ void stage_load(
    u32 sb, int slot,
    const u16* __restrict__ Ah, const u16* __restrict__ Bh,
    int mBase, int nBase, int K, int kt, int tid) {
    const u32 so = sb + slot * 32768;
    const int kOff = kt * 64;
#pragma unroll
    for (int j = 0; j < 4; j++) {
        const int id = tid + j * 256;          // 0..1023
        const int r = id >> 3, c = id & 7;
        const u32 dst = so + r * 128 + (((c ^ (r & 7)) & 7) << 4);
        cp16(dst,         Ah + (size_t)(mBase + r) * K + kOff + c * 8);
        cp16(dst + 16384, Bh + (size_t)(nBase + r) * K + kOff + c * 8);
    }
}

// ---------------- GEMM: 128x128 block, 8 warps (64x32 each), 1-term fp16 ----
// modes: 0 relu->hi plane, 3 attention, 4 final fused, 5 L3 combo, 6 raw->plain0
__global__ __launch_bounds__(256, 2)
void gemm_tc(const u16* __restrict__ Ahp, size_t aStrideZ, int aZmod,
             const u16* __restrict__ Bhp, size_t bStrideZ, int K,
             const float* __restrict__ bias0, const float* __restrict__ bias1,
             const float* __restrict__ bias2, int mode,
             u16* __restrict__ oH, size_t oStrideZ,
             float* __restrict__ plain0,
             u16* __restrict__ pH0, u16* __restrict__ pH1,
             const float* __restrict__ vatt, float* __restrict__ upart,
             const u16* __restrict__ p_arnh, const u16* __restrict__ p_addh,
             const float* __restrict__ p_cell, const float* __restrict__ p_eng,
             float* __restrict__ outH, float* __restrict__ outC) {
    extern __shared__ char smem[];
    const u32 sb = smem_u32(smem);
    const int tid = threadIdx.x, lane = tid & 31, warp = tid >> 5;
    const int warpM = warp >> 2, warpN = warp & 3;
    const int rowBase = warpM * 64, colBase = warpN * 32;
    const int nt = blockIdx.x, mt = blockIdx.y, z = blockIdx.z;
    const int mBase = mt * 128, nBase = nt * 128;

    const int az = aZmod ? (z % aZmod) : z;
    const u16* Ah = Ahp + (size_t)az * aStrideZ;
    const u16* Bh = Bhp + (size_t)z * bStrideZ;

    float acc[4][4][4];
#pragma unroll
    for (int i = 0; i < 4; i++)
#pragma unroll
        for (int j = 0; j < 4; j++)
#pragma unroll
            for (int k = 0; k < 4; k++) acc[i][j][k] = 0.0f;

    const int nk = K >> 6;

    stage_load(sb, 0, Ah, Bh, mBase, nBase, K, 0, tid);
    asm volatile("cp.async.commit_group;");
    stage_load(sb, 1, Ah, Bh, mBase, nBase, K, 1, tid);
    asm volatile("cp.async.commit_group;");

    const int arow = (lane & 15);
    const int acb  = (lane >> 4);
    const int brow = (lane & 7) + ((lane >> 4) << 3);
    const int bcb  = (lane >> 3) & 1;

    int slot = 0;
    for (int kt = 0; kt < nk; kt++) {
        if (kt + 1 < nk) asm volatile("cp.async.wait_group 1;");
        else             asm volatile("cp.async.wait_group 0;");
        __syncthreads();
        if (kt + 2 < nk) {
            int ps = slot + 2; if (ps >= 3) ps -= 3;
            stage_load(sb, ps, Ah, Bh, mBase, nBase, K, kt + 2, tid);
            asm volatile("cp.async.commit_group;");
        }
        const u32 so = sb + slot * 32768;
#pragma unroll
        for (int ks = 0; ks < 4; ks++) {
            u32 a_hi[4][4], b_hi[2][4];
#pragma unroll
            for (int mi = 0; mi < 4; mi++) {
                const int r = rowBase + mi * 16 + arow;
                const int c = ks * 2 + acb;
                ldsm4(a_hi[mi], so + r * 128 + (((c ^ (r & 7)) & 7) << 4));
            }
#pragma unroll
            for (int nj = 0; nj < 2; nj++) {
                const int r = colBase + nj * 16 + brow;
                const int c = ks * 2 + bcb;
                ldsm4(b_hi[nj], so + 16384 + r * 128 + (((c ^ (r & 7)) & 7) << 4));
            }
#pragma unroll
            for (int mi = 0; mi < 4; mi++)
#pragma unroll
                for (int ni = 0; ni < 4; ni++)
                    mma16816(acc[mi][ni], a_hi[mi], &b_hi[ni >> 1][(ni & 1) * 2]);
        }
        slot++; if (slot == 3) slot = 0;
    }

    // ---------------- epilogue ----------------
    const float* bias = (z == 0) ? bias0 : (z == 1) ? bias1 : bias2;
    if (mode == 3) {
        const float* qbz = plain0 + (size_t)z * 65536;   // qbias[z][128][512]
#pragma unroll
        for (int mi = 0; mi < 4; mi++) {
#pragma unroll
            for (int h = 0; h < 2; h++) {
                const int m = mBase + rowBase + mi * 16 + (lane >> 2) + h * 8;
                const float* qrow = qbz + (size_t)(m >> 5) * 512;
                float s = 0.0f;
#pragma unroll
                for (int ni = 0; ni < 4; ni++) {
                    const int n = nBase + colBase + ni * 8 + (lane & 3) * 2;
                    const float2 qv = *(const float2*)&qrow[n];
                    s += tanhf(acc[mi][ni][h * 2]     + qv.x) * vatt[z * 512 + n];
                    s += tanhf(acc[mi][ni][h * 2 + 1] + qv.y) * vatt[z * 512 + n + 1];
                }
                s += __shfl_xor_sync(0xffffffffu, s, 1);
                s += __shfl_xor_sync(0xffffffffu, s, 2);
                if ((lane & 3) == 0)
                    upart[((size_t)(nt * 4 + warpN) * 6 + z) * KBM + m] = s;
            }
        }
        return;
    }
#pragma unroll
    for (int mi = 0; mi < 4; mi++) {
#pragma unroll
        for (int h = 0; h < 2; h++) {
            const int m = mBase + rowBase + mi * 16 + (lane >> 2) + h * 8;
#pragma unroll
            for (int ni = 0; ni < 4; ni++) {
                const int n = nBase + colBase + ni * 8 + (lane & 3) * 2;
                float v0 = acc[mi][ni][h * 2];
                float v1 = acc[mi][ni][h * 2 + 1];
                if (mode != 6) { v0 += bias[n]; v1 += bias[n + 1]; }
                const size_t i0 = (size_t)m * 512 + n;
                if (mode == 6) {
                    *(float2*)&plain0[(size_t)z * 65536 + i0] = make_float2(v0, v1);
                } else if (mode == 4) {
                    const float e = p_eng[m];
                    const float wc0 = 1.0f / (1.0f + expf(-v0));
                    const float wc1 = 1.0f / (1.0f + expf(-v1));
                    const float2 cc = *(const float2*)&p_cell[i0];
                    const float2 aa = __half22float2(*(const __half2*)&p_arnh[i0]);
                    const float2 dd = __half22float2(*(const __half2*)&p_addh[i0]);
                    const float uc0 = cc.x + aa.x * dd.x * e;
                    const float uc1 = cc.y + aa.y * dd.y * e;
                    *(float2*)&outC[i0] = make_float2(uc0, uc1);
                    *(float2*)&outH[i0] = make_float2(wc0 * tanhf(uc0), wc1 * tanhf(uc1));
                } else if (mode == 5 && z < 2) {
                    u16* pl = (z == 0) ? pH0 : pH1;
                    if (z == 0) { v0 = 1.0f / (1.0f + expf(-v0)); v1 = 1.0f / (1.0f + expf(-v1)); }
                    else        { v0 = tanhf(v0); v1 = tanhf(v1); }
                    *(u32*)&pl[i0] = cvt2(v0, v1);
                } else {
                    v0 = fmaxf(v0, 0.0f); v1 = fmaxf(v1, 0.0f);
                    u16* dH = oH + (mode == 5 ? 0 : (size_t)z * oStrideZ);
                    *(u32*)&dH[i0] = cvt2(v0, v1);
                }
            }
        }
    }
}

// ---------------- merged weight prepack ---------------------------------------
struct PrepackDesc { const float* s0; const float* s1; size_t off; int K; };
struct PrepackParams { PrepackDesc d[12]; };

__global__ void prepack_all(PrepackParams p) {
    __shared__ float t[32][33];
    const PrepackDesc de = p.d[blockIdx.z];
    const int K = de.K;
    const int k0 = blockIdx.x * 32;
    if (k0 >= K) return;
    const int n0 = blockIdx.y * 32;
    const int tx = threadIdx.x, ty = threadIdx.y;
#pragma unroll
    for (int i = 0; i < 4; i++) {
        const int k = k0 + ty + i * 8;
        t[ty + i * 8][tx] = (k < 512) ? de.s0[(size_t)k * 512 + n0 + tx]
                                      : de.s1[(size_t)(k - 512) * 512 + n0 + tx];
    }
    __syncthreads();
#pragma unroll
    for (int i = 0; i < 4; i++) {
        const int n = n0 + ty + i * 8;
        const int k = k0 + tx;
        u16 h, l; split2(t[tx][ty + i * 8], h, l);
        g_wbh[de.off + (size_t)n * K + k] = h;
        g_wbl[de.off + (size_t)n * K + k] = l;
    }
}

// ---------------- activation converters (MLP=4 per thread) --------------------
// each thread: 16 consecutive floats (4 independent float4 loads)
__global__ void convert_info(const float* __restrict__ x, const float* __restrict__ h,
                             u16* __restrict__ dh) {
    const size_t id = (size_t)blockIdx.x * 256 + threadIdx.x;
    const int m  = (int)(id >> 6);
    const int kq = ((int)id & 63) << 4;
    const float* src = (kq < 512) ? (x + (size_t)m * 512 + kq)
                                  : (h + (size_t)m * 512 + (kq - 512));
    float4 v0 = *(const float4*)(src);
    float4 v1 = *(const float4*)(src + 4);
    float4 v2 = *(const float4*)(src + 8);
    float4 v3 = *(const float4*)(src + 12);
    uint4 o0, o1;
    o0.x = cvt2(v0.x, v0.y); o0.y = cvt2(v0.z, v0.w);
    o0.z = cvt2(v1.x, v1.y); o0.w = cvt2(v1.z, v1.w);
    o1.x = cvt2(v2.x, v2.y); o1.y = cvt2(v2.z, v2.w);
    o1.z = cvt2(v3.x, v3.y); o1.w = cvt2(v3.z, v3.w);
    *(uint4*)&dh[(size_t)m * 1024 + kq]     = o0;
    *(uint4*)&dh[(size_t)m * 1024 + kq + 8] = o1;
}
__global__ void convert_att(const float* __restrict__ kbk, const float* __restrict__ q) {
    const int y = blockIdx.y;
    const size_t id = (size_t)blockIdx.x * 256 + threadIdx.x;
    const int m  = (int)(id >> 5);
    const int kq = ((int)id & 31) << 4;
    const float* src;
    u16* dh;
    if (y < 3) {
        src = kbk + ((size_t)y * 4096 + m) * 512 + kq;
        dh = g_atth + (size_t)y * ATTZ;
    } else {
        if (m >= 128) return;
        src = q + (size_t)m * 512 + kq;
        dh = g_qh;
    }
    float4 v0 = *(const float4*)(src);
    float4 v1 = *(const float4*)(src + 4);
    float4 v2 = *(const float4*)(src + 8);
    float4 v3 = *(const float4*)(src + 12);
    uint4 o0, o1;
    o0.x = cvt2(v0.x, v0.y); o0.y = cvt2(v0.z, v0.w);
    o0.z = cvt2(v1.x, v1.y); o0.w = cvt2(v1.z, v1.w);
    o1.x = cvt2(v2.x, v2.y); o1.y = cvt2(v2.z, v2.w);
    o1.z = cvt2(v3.x, v3.y); o1.w = cvt2(v3.z, v3.w);
    *(uint4*)&dh[(size_t)m * 512 + kq]     = o0;
    *(uint4*)&dh[(size_t)m * 512 + kq + 8] = o1;
}

// ---------------- small kernels -------------------------------------------------
__global__ void eng_kernel(const float* __restrict__ cell, const float* __restrict__ w,
                           float* __restrict__ eng) {
    const int row = blockIdx.x * 8 + (threadIdx.x >> 5);
    const int lane = threadIdx.x & 31;
    const float* c = cell + (size_t)row * HD;
    float s = 0.0f;
#pragma unroll 4
    for (int k = lane; k < HD; k += 32) s += c[k] * w[k];
#pragma unroll
    for (int o = 16; o; o >>= 1) s += __shfl_down_sync(0xffffffffu, s, o);
    if (!lane) eng[row] = s;
}
__global__ void detect_mask_kernel(const unsigned int* __restrict__ w) {
    __shared__ int sF, sG;
    if (threadIdx.x == 0) { sF = 0; sG = 0; }
    __syncthreads();
    int f = 0, g = 0;
    for (int i = threadIdx.x; i < 65536; i += blockDim.x) {
        const unsigned int v = w[i];
        if (v == 0x3F800000u) f = 1;
        else if (v > 1u) g = 1;
    }
    if (f) atomicOr(&sF, 1);
    if (g) atomicOr(&sG, 1);
    __syncthreads();
    if (threadIdx.x == 0) g_maskmode = sF ? 2 : (sG ? 0 : 1);
}
__global__ void utk_kernel(const float* __restrict__ up, const void* __restrict__ maskraw,
                           float* __restrict__ out) {
    __shared__ float S[3][32];
    const int b = blockIdx.y;
    if (threadIdx.x < 96) {
        const int d = threadIdx.x >> 5, i = threadIdx.x & 31;
        float s = 0.0f;
#pragma unroll
        for (int p = 0; p < 16; p++)
#pragma unroll
            for (int hop = 0; hop < 2; hop++)
                s += up[((size_t)p * 6 + hop * 3 + d) * KBM + b * 32 + i];
        S[d][i] = s;
    }
    __syncthreads();
    const int mode = g_maskmode;
    const int j = blockIdx.x * 256 + threadIdx.x;
    const float v = S[0][j >> 10] + S[1][(j >> 5) & 31] + S[2][j & 31];
    const size_t o = (size_t)b * KBTOT + j;
    bool msk;
    if (mode == 0)      msk = ((const unsigned char*)maskraw)[o] != 0;
    else if (mode == 1) msk = ((const int*)maskraw)[o] != 0;
    else                msk = ((const float*)maskraw)[o] != 0.0f;
    out[o] = msk ? 0.0f : v;
}

// ---------------- host -----------------------------------------------------------
extern "C" void kernel_launch(void* const* d_in, const int* in_sizes, int n_in,
                              void* d_out, int out_size) {
    const float* query   = (const float*)d_in[0];
    const float* kb_keys = (const float*)d_in[1];
    const float* Wq      = (const float*)d_in[2];
    const float* Wk      = (const float*)d_in[3];
    const float* v_att   = (const float*)d_in[4];
    const float* x       = (const float*)d_in[5];
    const float* hidden  = (const float*)d_in[6];
    const float* cell    = (const float*)d_in[7];
    const float* arn_w1  = (const float*)d_in[8];
    const float* arn_b1  = (const float*)d_in[9];
    const float* arn_w2  = (const float*)d_in[10];
    const float* arn_b2  = (const float*)d_in[11];
    const float* arn_w3  = (const float*)d_in[12];
    const float* arn_b3  = (const float*)d_in[13];
    const float* add_w1  = (const float*)d_in[14];
    const float* add_b1  = (const float*)d_in[15];
    const float* add_w2  = (const float*)d_in[16];
    const float* add_b2  = (const float*)d_in[17];
    const float* add_w3  = (const float*)d_in[18];
    const float* add_b3  = (const float*)d_in[19];
    const float* eng_w   = (const float*)d_in[20];
    const float* wc_w1   = (const float*)d_in[21];
    const float* wc_b1   = (const float*)d_in[22];
    const float* wc_w2   = (const float*)d_in[23];
    const float* wc_b2   = (const float*)d_in[24];
    const float* wc_w3   = (const float*)d_in[25];
    const float* wc_b3   = (const float*)d_in[26];
    const float* wc_w4   = (const float*)d_in[27];
    const float* wc_b4   = (const float*)d_in[28];
    const void*  kb_mask = d_in[29];

    float* out     = (float*)d_out;
    float* out_utk = out;
    float* outH    = out + (size_t)BSZ * KBTOT;
    float* outC    = outH + (size_t)BT * HD;

    u16 *wbh, *atth, *qh, *ah, *arnh, *addh;
    float *qb, *upart, *engp;
    cudaGetSymbolAddress((void**)&wbh,  g_wbh);
    cudaGetSymbolAddress((void**)&atth, g_atth);
    cudaGetSymbolAddress((void**)&qh,   g_qh);
    cudaGetSymbolAddress((void**)&ah,   g_ah);
    cudaGetSymbolAddress((void**)&arnh, g_arnh);
    cudaGetSymbolAddress((void**)&addh, g_addh);
    cudaGetSymbolAddress((void**)&qb,   g_qb);
    cudaGetSymbolAddress((void**)&upart,g_upart);
    cudaGetSymbolAddress((void**)&engp, g_eng);

    static cudaStream_t s2 = nullptr, s3 = nullptr;
    static cudaEvent_t evFork = nullptr, evJoin = nullptr, evJoin3 = nullptr;
    if (!s2) {
        cudaFuncSetAttribute(gemm_tc, cudaFuncAttributeMaxDynamicSharedMemorySize, 98304);
        cudaStreamCreateWithFlags(&s2, cudaStreamNonBlocking);
        cudaStreamCreateWithFlags(&s3, cudaStreamNonBlocking);
        cudaEventCreateWithFlags(&evFork, cudaEventDisableTiming);
        cudaEventCreateWithFlags(&evJoin, cudaEventDisableTiming);
        cudaEventCreateWithFlags(&evJoin3, cudaEventDisableTiming);
    }

    // ---- fork immediately --------------------------------------------------------
    cudaEventRecord(evFork, 0);
    cudaStreamWaitEvent(s2, evFork, 0);
    cudaStreamWaitEvent(s3, evFork, 0);

    // s2: attention chain
    PrepackParams pa;
    for (int i = 0; i < 6; i++) {
        pa.d[i]     = {Wk + (size_t)i * 262144, Wk + (size_t)i * 262144, WKOFF + i * SMALL, 512};
        pa.d[6 + i] = {Wq + (size_t)i * 262144, Wq + (size_t)i * 262144, WQOFF + i * SMALL, 512};
    }
    prepack_all<<<dim3(16, 16, 12), dim3(32, 8), 0, s2>>>(pa);
    convert_att<<<dim3(512, 4), 256, 0, s2>>>(kb_keys, query);
    gemm_tc<<<dim3(4, 1, 6), 256, 98304, s2>>>(
        qh, 0, 1, wbh + WQOFF, SMALL, 512,
        nullptr, nullptr, nullptr, 6,
        nullptr, 0, qb, nullptr, nullptr, nullptr, nullptr,
        nullptr, nullptr, nullptr, nullptr, nullptr, nullptr);
    gemm_tc<<<dim3(4, 32, 6), 256, 98304, s2>>>(
        atth, ATTZ, 3, wbh + WKOFF, SMALL, 512,
        nullptr, nullptr, nullptr, 3,
        nullptr, 0, qb, nullptr, nullptr, v_att, upart,
        nullptr, nullptr, nullptr, nullptr, nullptr, nullptr);
    detect_mask_kernel<<<1, 1024, 0, s2>>>((const unsigned int*)kb_mask);
    utk_kernel<<<dim3(KBTOT / 256, BSZ), 256, 0, s2>>>(upart, kb_mask, out_utk);
    cudaEventRecord(evJoin, s2);

    // s3: MLP input conversion + eng (overlaps MLP prepack on main)
    convert_info<<<8192, 256, 0, s3>>>(x, hidden, ah);
    eng_kernel<<<BT / 8, 256, 0, s3>>>(cell, eng_w, engp);
    cudaEventRecord(evJoin3, s3);

    // main: MLP weight prepack
    PrepackParams pm;
    pm.d[0] = {arn_w1, arn_w1 + 262144, W1OFF + 0 * BIG, 1024};
    pm.d[1] = {add_w1, add_w1 + 262144, W1OFF + 1 * BIG, 1024};
    pm.d[2] = {wc_w1,  wc_w1  + 262144, W1OFF + 2 * BIG, 1024};
    const float* sw[7] = {arn_w2, arn_w3, add_w2, add_w3, wc_w2, wc_w3, wc_w4};
    for (int j = 0; j < 7; j++)
        pm.d[3 + j] = {sw[j], sw[j], WSOFF2 + j * SMALL, 512};
    for (int j = 10; j < 12; j++) pm.d[j] = pm.d[9];
    prepack_all<<<dim3(32, 16, 10), dim3(32, 8)>>>(pm);
    cudaStreamWaitEvent(0, evJoin3, 0);

    // L1: info @ w1 -> h1 hi planes (relu)
    gemm_tc<<<dim3(4, 256, 3), 256, 98304>>>(
        ah, 0, 0, wbh + W1OFF, BIG, 1024,
        arn_b1, add_b1, wc_b1, 0,
        ah + H1_OFF, H1S, nullptr, nullptr, nullptr, nullptr, nullptr,
        nullptr, nullptr, nullptr, nullptr, nullptr, nullptr);
    // L2: h1 @ w2 -> h2 hi planes (relu)
    gemm_tc<<<dim3(4, 256, 3), 256, 98304>>>(
        ah + H1_OFF, H1S, 0, wbh + WSOFF2, 2 * SMALL, 512,
        arn_b2, add_b2, wc_b2, 0,
        ah + H2_OFF, H1S, nullptr, nullptr, nullptr, nullptr, nullptr,
        nullptr, nullptr, nullptr, nullptr, nullptr, nullptr);
    // L3: h2 @ w3; z0 sigmoid->arnh(fp16), z1 tanh->addh(fp16), z2 relu->h3 plane
    gemm_tc<<<dim3(4, 256, 3), 256, 98304>>>(
        ah + H2_OFF, H1S, 0, wbh + WSOFF2 + SMALL, 2 * SMALL, 512,
        arn_b3, add_b3, wc_b3, 5,
        ah + H1_OFF, 0, nullptr, arnh, addh, nullptr, nullptr,
        nullptr, nullptr, nullptr, nullptr, nullptr, nullptr);
    // L4: h3 @ wc_w4 -> fused final epilogue
    gemm_tc<<<dim3(4, 256, 1), 256, 98304>>>(
        ah + H1_OFF, 0, 0, wbh + WSOFF2 + 6 * SMALL, SMALL, 512,
        wc_b4, wc_b4, wc_b4, 4,
        nullptr, 0, nullptr, nullptr, nullptr, nullptr, nullptr,
        arnh, addh, cell, engp, outH, outC);

    // ---- join ---------------------------------------------------------------------
    cudaStreamWaitEvent(0, evJoin, 0);
}

// round 15
// speedup vs baseline: 1.4664x; 1.4664x over previous
#include <cuda_runtime.h>
#include <cuda_fp16.h>
#include <cstdint>

#define HD 512
#define BT 32768
#define BSZ 128
#define KBM 4096
#define KBTOT 32768

typedef unsigned int u32;
typedef unsigned long long u64;
typedef unsigned short u16;

// weight plane slot offsets (elements)
#define BIG    524288ULL                  // 512n x 1024k
#define SMALL  262144ULL                  // 512n x 512k
#define W1OFF  0ULL                       // 3 BIG: arn1, add1, wc1
#define WKOFF  (3ULL*BIG)                 // 6 SMALL Wk
#define WQOFF  (WKOFF + 6ULL*SMALL)       // 6 SMALL Wq
#define WSOFF2 (WQOFF + 6ULL*SMALL)       // 7 SMALL: arn2,arn3,add2,add3,wc2,wc3,wc4
#define WTOT   (WSOFF2 + 7ULL*SMALL)

#define ATTZ   2097152ULL                 // 4096 x 512 per dim
#define H1S    16777216ULL                // 32768 x 512
#define H1_OFF 33554432ULL
#define H2_OFF (H1_OFF + 3*H1S)

__device__ u16   g_wbh[WTOT];
__device__ u16   g_wbl[WTOT];
__device__ u16   g_atth[3*ATTZ];
__device__ u16   g_qh[65536];
__device__ u16   g_ah[134217728];         // hi planes: info + h1[3] + h2[3] (+h3)
__device__ float g_qb[6*128*512];
__device__ u16   g_arnh[(size_t)BT*HD];
__device__ u16   g_addh[(size_t)BT*HD];
__device__ float g_upart[16*6*KBM];
__device__ float g_eng[BT];
__device__ int   g_maskmode;

__device__ __forceinline__ void split2(float v, u16& h, u16& l) {
    __half hh = __float2half_rn(v);
    h = __half_as_ushort(hh);
    l = __half_as_ushort(__float2half_rn(v - __half2float(hh)));
}
__device__ __forceinline__ u32 cvt2(float v0, float v1) {
    u32 r;
    asm("cvt.rn.f16x2.f32 %0, %1, %2;" : "=r"(r) : "f"(v1), "f"(v0));
    return r;
}
__device__ __forceinline__ u32 smem_u32(const void* p) {
    u32 a;
    asm("{ .reg .u64 t; cvta.to.shared.u64 t, %1; cvt.u32.u64 %0, t; }" : "=r"(a) : "l"(p));
    return a;
}
__device__ __forceinline__ void cp16(u32 dst, const void* src) {
    asm volatile("cp.async.cg.shared.global [%0], [%1], 16;" :: "r"(dst), "l"(src));
}
__device__ __forceinline__ void ldsm4(u32* r, u32 a) {
    asm volatile("ldmatrix.sync.aligned.m8n8.x4.shared.b16 {%0,%1,%2,%3}, [%4];"
                 : "=r"(r[0]), "=r"(r[1]), "=r"(r[2]), "=r"(r[3]) : "r"(a));
}
__device__ __forceinline__ void mma16816(float* c, const u32* a, const u32* b) {
    asm volatile("mma.sync.aligned.m16n8k16.row.col.f32.f16.f16.f32 "
                 "{%0,%1,%2,%3},{%4,%5,%6,%7},{%8,%9},{%0,%1,%2,%3};"
                 : "+f"(c[0]), "+f"(c[1]), "+f"(c[2]), "+f"(c[3])
                 : "r"(a[0]), "r"(a[1]), "r"(a[2]), "r"(a[3]), "r"(b[0]), "r"(b[1]));
}

// ---------------- stage loader: k-tile 64, 128B rows, chunk^(row&7) swizzle --
// A-hi @0 (16KB), B-hi @16384; stage stride 32768; 3 stages; 256 threads.
__device__ __forceinline__ void stage_load(
    u32 sb, int slot,
    const u16* __restrict__ Ah, const u16* __restrict__ Bh,
    int mBase, int nBase, int K, int kt, int tid) {
    const u32 so = sb + slot * 32768;
    const int kOff = kt * 64;
#pragma unroll
    for (int j = 0; j < 4; j++) {
        const int id = tid + j * 256;          // 0..1023
        const int r = id >> 3, c = id & 7;
        const u32 dst = so + r * 128 + (((c ^ (r & 7)) & 7) << 4);
        cp16(dst,         Ah + (size_t)(mBase + r) * K + kOff + c * 8);
        cp16(dst + 16384, Bh + (size_t)(nBase + r) * K + kOff + c * 8);
    }
}

// ---------------- GEMM: 128x128 block, 8 warps (64x32 each), 1-term fp16 ----
// modes: 0 relu->hi plane, 3 attention, 4 final fused, 5 L3 combo, 6 raw->plain0
__global__ __launch_bounds__(256, 2)
void gemm_tc(const u16* __restrict__ Ahp, size_t aStrideZ, int aZmod,
             const u16* __restrict__ Bhp, size_t bStrideZ, int K,
             const float* __restrict__ bias0, const float* __restrict__ bias1,
             const float* __restrict__ bias2, int mode,
             u16* __restrict__ oH, size_t oStrideZ,
             float* __restrict__ plain0,
             u16* __restrict__ pH0, u16* __restrict__ pH1,
             const float* __restrict__ vatt, float* __restrict__ upart,
             const u16* __restrict__ p_arnh, const u16* __restrict__ p_addh,
             const float* __restrict__ p_cell, const float* __restrict__ p_eng,
             float* __restrict__ outH, float* __restrict__ outC) {
    extern __shared__ char smem[];
    const u32 sb = smem_u32(smem);
    const int tid = threadIdx.x, lane = tid & 31, warp = tid >> 5;
    const int warpM = warp >> 2, warpN = warp & 3;
    const int rowBase = warpM * 64, colBase = warpN * 32;
    const int nt = blockIdx.x, mt = blockIdx.y, z = blockIdx.z;
    const int mBase = mt * 128, nBase = nt * 128;

    const int az = aZmod ? (z % aZmod) : z;
    const u16* Ah = Ahp + (size_t)az * aStrideZ;
    const u16* Bh = Bhp + (size_t)z * bStrideZ;

    float acc[4][4][4];
#pragma unroll
    for (int i = 0; i < 4; i++)
#pragma unroll
        for (int j = 0; j < 4; j++)
#pragma unroll
            for (int k = 0; k < 4; k++) acc[i][j][k] = 0.0f;

    const int nk = K >> 6;

    stage_load(sb, 0, Ah, Bh, mBase, nBase, K, 0, tid);
    asm volatile("cp.async.commit_group;");
    stage_load(sb, 1, Ah, Bh, mBase, nBase, K, 1, tid);
    asm volatile("cp.async.commit_group;");

    const int arow = (lane & 15);
    const int acb  = (lane >> 4);
    const int brow = (lane & 7) + ((lane >> 4) << 3);
    const int bcb  = (lane >> 3) & 1;

    int slot = 0;
    for (int kt = 0; kt < nk; kt++) {
        if (kt + 1 < nk) asm volatile("cp.async.wait_group 1;");
        else             asm volatile("cp.async.wait_group 0;");
        __syncthreads();
        if (kt + 2 < nk) {
            int ps = slot + 2; if (ps >= 3) ps -= 3;
            stage_load(sb, ps, Ah, Bh, mBase, nBase, K, kt + 2, tid);
            asm volatile("cp.async.commit_group;");
        }
        const u32 so = sb + slot * 32768;
#pragma unroll
        for (int ks = 0; ks < 4; ks++) {
            u32 a_hi[4][4], b_hi[2][4];
#pragma unroll
            for (int mi = 0; mi < 4; mi++) {
                const int r = rowBase + mi * 16 + arow;
                const int c = ks * 2 + acb;
                ldsm4(a_hi[mi], so + r * 128 + (((c ^ (r & 7)) & 7) << 4));
            }
#pragma unroll
            for (int nj = 0; nj < 2; nj++) {
                const int r = colBase + nj * 16 + brow;
                const int c = ks * 2 + bcb;
                ldsm4(b_hi[nj], so + 16384 + r * 128 + (((c ^ (r & 7)) & 7) << 4));
            }
#pragma unroll
            for (int mi = 0; mi < 4; mi++)
#pragma unroll
                for (int ni = 0; ni < 4; ni++)
                    mma16816(acc[mi][ni], a_hi[mi], &b_hi[ni >> 1][(ni & 1) * 2]);
        }
        slot++; if (slot == 3) slot = 0;
    }

    // ---------------- epilogue ----------------
    const float* bias = (z == 0) ? bias0 : (z == 1) ? bias1 : bias2;
    if (mode == 3) {
        const float* qbz = plain0 + (size_t)z * 65536;   // qbias[z][128][512]
#pragma unroll
        for (int mi = 0; mi < 4; mi++) {
#pragma unroll
            for (int h = 0; h < 2; h++) {
                const int m = mBase + rowBase + mi * 16 + (lane >> 2) + h * 8;
                const float* qrow = qbz + (size_t)(m >> 5) * 512;
                float s = 0.0f;
#pragma unroll
                for (int ni = 0; ni < 4; ni++) {
                    const int n = nBase + colBase + ni * 8 + (lane & 3) * 2;
                    const float2 qv = *(const float2*)&qrow[n];
                    s += tanhf(acc[mi][ni][h * 2]     + qv.x) * vatt[z * 512 + n];
                    s += tanhf(acc[mi][ni][h * 2 + 1] + qv.y) * vatt[z * 512 + n + 1];
                }
                s += __shfl_xor_sync(0xffffffffu, s, 1);
                s += __shfl_xor_sync(0xffffffffu, s, 2);
                if ((lane & 3) == 0)
                    upart[((size_t)(nt * 4 + warpN) * 6 + z) * KBM + m] = s;
            }
        }
        return;
    }
#pragma unroll
    for (int mi = 0; mi < 4; mi++) {
#pragma unroll
        for (int h = 0; h < 2; h++) {
            const int m = mBase + rowBase + mi * 16 + (lane >> 2) + h * 8;
#pragma unroll
            for (int ni = 0; ni < 4; ni++) {
                const int n = nBase + colBase + ni * 8 + (lane & 3) * 2;
                float v0 = acc[mi][ni][h * 2];
                float v1 = acc[mi][ni][h * 2 + 1];
                if (mode != 6) { v0 += bias[n]; v1 += bias[n + 1]; }
                const size_t i0 = (size_t)m * 512 + n;
                if (mode == 6) {
                    *(float2*)&plain0[(size_t)z * 65536 + i0] = make_float2(v0, v1);
                } else if (mode == 4) {
                    const float e = p_eng[m];
                    const float wc0 = 1.0f / (1.0f + expf(-v0));
                    const float wc1 = 1.0f / (1.0f + expf(-v1));
                    const float2 cc = *(const float2*)&p_cell[i0];
                    const float2 aa = __half22float2(*(const __half2*)&p_arnh[i0]);
                    const float2 dd = __half22float2(*(const __half2*)&p_addh[i0]);
                    const float uc0 = cc.x + aa.x * dd.x * e;
                    const float uc1 = cc.y + aa.y * dd.y * e;
                    *(float2*)&outC[i0] = make_float2(uc0, uc1);
                    *(float2*)&outH[i0] = make_float2(wc0 * tanhf(uc0), wc1 * tanhf(uc1));
                } else if (mode == 5 && z < 2) {
                    u16* pl = (z == 0) ? pH0 : pH1;
                    if (z == 0) { v0 = 1.0f / (1.0f + expf(-v0)); v1 = 1.0f / (1.0f + expf(-v1)); }
                    else        { v0 = tanhf(v0); v1 = tanhf(v1); }
                    *(u32*)&pl[i0] = cvt2(v0, v1);
                } else {
                    v0 = fmaxf(v0, 0.0f); v1 = fmaxf(v1, 0.0f);
                    u16* dH = oH + (mode == 5 ? 0 : (size_t)z * oStrideZ);
                    *(u32*)&dH[i0] = cvt2(v0, v1);
                }
            }
        }
    }
}

// ---------------- merged weight prepack ---------------------------------------
struct PrepackDesc { const float* s0; const float* s1; size_t off; int K; };
struct PrepackParams { PrepackDesc d[12]; };

__global__ void prepack_all(PrepackParams p) {
    __shared__ float t[32][33];
    const PrepackDesc de = p.d[blockIdx.z];
    const int K = de.K;
    const int k0 = blockIdx.x * 32;
    if (k0 >= K) return;
    const int n0 = blockIdx.y * 32;
    const int tx = threadIdx.x, ty = threadIdx.y;
#pragma unroll
    for (int i = 0; i < 4; i++) {
        const int k = k0 + ty + i * 8;
        t[ty + i * 8][tx] = (k < 512) ? de.s0[(size_t)k * 512 + n0 + tx]
                                      : de.s1[(size_t)(k - 512) * 512 + n0 + tx];
    }
    __syncthreads();
#pragma unroll
    for (int i = 0; i < 4; i++) {
        const int n = n0 + ty + i * 8;
        const int k = k0 + tx;
        u16 h, l; split2(t[tx][ty + i * 8], h, l);
        g_wbh[de.off + (size_t)n * K + k] = h;
        g_wbl[de.off + (size_t)n * K + k] = l;
    }
}

// ---------------- activation converters (MLP=4, coalesced) --------------------
// one block = 4 rows; thread t handles float4 #t of each row (coalesced per row)
__global__ void convert_info(const float* __restrict__ x, const float* __restrict__ h,
                             u16* __restrict__ dh) {
    const int t = threadIdx.x;          // 0..255, float4 index within 1024-float row
    const int k = t << 2;
    const int m0 = blockIdx.x << 2;
    const float* src = (k < 512) ? (x + k) : (h + k - 512);
    float4 v[4];
#pragma unroll
    for (int r = 0; r < 4; r++)
        v[r] = *(const float4*)(src + (size_t)(m0 + r) * 512);
#pragma unroll
    for (int r = 0; r < 4; r++) {
        const u64 hw = (u64)cvt2(v[r].x, v[r].y) | ((u64)cvt2(v[r].z, v[r].w) << 32);
        *(u64*)&dh[(size_t)(m0 + r) * 1024 + k] = hw;
    }
}
__global__ void convert_att(const float* __restrict__ kbk, const float* __restrict__ q) {
    const int y = blockIdx.y;
    const int t = threadIdx.x;          // 0..127, float4 index within 512-float row
    const int k = t << 2;
    const int m0 = blockIdx.x << 2;
    const float* src;
    u16* dh;
    if (y < 3) {
        src = kbk + (size_t)y * 4096 * 512 + k;
        dh = g_atth + (size_t)y * ATTZ;
    } else {
        if (m0 >= 128) return;
        src = q + k;
        dh = g_qh;
    }
    float4 v[4];
#pragma unroll
    for (int r = 0; r < 4; r++)
        v[r] = *(const float4*)(src + (size_t)(m0 + r) * 512);
#pragma unroll
    for (int r = 0; r < 4; r++) {
        const u64 hw = (u64)cvt2(v[r].x, v[r].y) | ((u64)cvt2(v[r].z, v[r].w) << 32);
        *(u64*)&dh[(size_t)(m0 + r) * 512 + k] = hw;
    }
}

// ---------------- small kernels -------------------------------------------------
__global__ void eng_kernel(const float* __restrict__ cell, const float* __restrict__ w,
                           float* __restrict__ eng) {
    const int row = blockIdx.x * 8 + (threadIdx.x >> 5);
    const int lane = threadIdx.x & 31;
    const float* c = cell + (size_t)row * HD;
    float s = 0.0f;
#pragma unroll 4
    for (int k = lane; k < HD; k += 32) s += c[k] * w[k];
#pragma unroll
    for (int o = 16; o; o >>= 1) s += __shfl_down_sync(0xffffffffu, s, o);
    if (!lane) eng[row] = s;
}
__global__ void detect_mask_kernel(const unsigned int* __restrict__ w) {
    __shared__ int sF, sG;
    if (threadIdx.x == 0) { sF = 0; sG = 0; }
    __syncthreads();
    int f = 0, g = 0;
    for (int i = threadIdx.x; i < 65536; i += blockDim.x) {
        const unsigned int v = w[i];
        if (v == 0x3F800000u) f = 1;
        else if (v > 1u) g = 1;
    }
    if (f) atomicOr(&sF, 1);
    if (g) atomicOr(&sG, 1);
    __syncthreads();
    if (threadIdx.x == 0) g_maskmode = sF ? 2 : (sG ? 0 : 1);
}
__global__ void utk_kernel(const float* __restrict__ up, const void* __restrict__ maskraw,
                           float* __restrict__ out) {
    __shared__ float S[3][32];
    const int b = blockIdx.y;
    if (threadIdx.x < 96) {
        const int d = threadIdx.x >> 5, i = threadIdx.x & 31;
        float s = 0.0f;
#pragma unroll
        for (int p = 0; p < 16; p++)
#pragma unroll
            for (int hop = 0; hop < 2; hop++)
                s += up[((size_t)p * 6 + hop * 3 + d) * KBM + b * 32 + i];
        S[d][i] = s;
    }
    __syncthreads();
    const int mode = g_maskmode;
    const int j = blockIdx.x * 256 + threadIdx.x;
    const float v = S[0][j >> 10] + S[1][(j >> 5) & 31] + S[2][j & 31];
    const size_t o = (size_t)b * KBTOT + j;
    bool msk;
    if (mode == 0)      msk = ((const unsigned char*)maskraw)[o] != 0;
    else if (mode == 1) msk = ((const int*)maskraw)[o] != 0;
    else                msk = ((const float*)maskraw)[o] != 0.0f;
    out[o] = msk ? 0.0f : v;
}

// ---------------- host -----------------------------------------------------------
extern "C" void kernel_launch(void* const* d_in, const int* in_sizes, int n_in,
                              void* d_out, int out_size) {
    const float* query   = (const float*)d_in[0];
    const float* kb_keys = (const float*)d_in[1];
    const float* Wq      = (const float*)d_in[2];
    const float* Wk      = (const float*)d_in[3];
    const float* v_att   = (const float*)d_in[4];
    const float* x       = (const float*)d_in[5];
    const float* hidden  = (const float*)d_in[6];
    const float* cell    = (const float*)d_in[7];
    const float* arn_w1  = (const float*)d_in[8];
    const float* arn_b1  = (const float*)d_in[9];
    const float* arn_w2  = (const float*)d_in[10];
    const float* arn_b2  = (const float*)d_in[11];
    const float* arn_w3  = (const float*)d_in[12];
    const float* arn_b3  = (const float*)d_in[13];
    const float* add_w1  = (const float*)d_in[14];
    const float* add_b1  = (const float*)d_in[15];
    const float* add_w2  = (const float*)d_in[16];
    const float* add_b2  = (const float*)d_in[17];
    const float* add_w3  = (const float*)d_in[18];
    const float* add_b3  = (const float*)d_in[19];
    const float* eng_w   = (const float*)d_in[20];
    const float* wc_w1   = (const float*)d_in[21];
    const float* wc_b1   = (const float*)d_in[22];
    const float* wc_w2   = (const float*)d_in[23];
    const float* wc_b2   = (const float*)d_in[24];
    const float* wc_w3   = (const float*)d_in[25];
    const float* wc_b3   = (const float*)d_in[26];
    const float* wc_w4   = (const float*)d_in[27];
    const float* wc_b4   = (const float*)d_in[28];
    const void*  kb_mask = d_in[29];

    float* out     = (float*)d_out;
    float* out_utk = out;
    float* outH    = out + (size_t)BSZ * KBTOT;
    float* outC    = outH + (size_t)BT * HD;

    u16 *wbh, *atth, *qh, *ah, *arnh, *addh;
    float *qb, *upart, *engp;
    cudaGetSymbolAddress((void**)&wbh,  g_wbh);
    cudaGetSymbolAddress((void**)&atth, g_atth);
    cudaGetSymbolAddress((void**)&qh,   g_qh);
    cudaGetSymbolAddress((void**)&ah,   g_ah);
    cudaGetSymbolAddress((void**)&arnh, g_arnh);
    cudaGetSymbolAddress((void**)&addh, g_addh);
    cudaGetSymbolAddress((void**)&qb,   g_qb);
    cudaGetSymbolAddress((void**)&upart,g_upart);
    cudaGetSymbolAddress((void**)&engp, g_eng);

    static cudaStream_t s2 = nullptr;
    static cudaEvent_t evFork = nullptr, evJoin = nullptr;
    if (!s2) {
        cudaFuncSetAttribute(gemm_tc, cudaFuncAttributeMaxDynamicSharedMemorySize, 98304);
        cudaStreamCreateWithFlags(&s2, cudaStreamNonBlocking);
        cudaEventCreateWithFlags(&evFork, cudaEventDisableTiming);
        cudaEventCreateWithFlags(&evJoin, cudaEventDisableTiming);
    }

    // ---- fork immediately: attention chain fully parallel with MLP chain --------
    cudaEventRecord(evFork, 0);
    cudaStreamWaitEvent(s2, evFork, 0);

    // s2: attention weight prepack (12 SMALL slots: Wk, Wq)
    PrepackParams pa;
    for (int i = 0; i < 6; i++) {
        pa.d[i]     = {Wk + (size_t)i * 262144, Wk + (size_t)i * 262144, WKOFF + i * SMALL, 512};
        pa.d[6 + i] = {Wq + (size_t)i * 262144, Wq + (size_t)i * 262144, WQOFF + i * SMALL, 512};
    }
    prepack_all<<<dim3(16, 16, 12), dim3(32, 8), 0, s2>>>(pa);
    convert_att<<<dim3(1024, 4), 128, 0, s2>>>(kb_keys, query);
    // qbias[z] = query @ Wq[z]
    gemm_tc<<<dim3(4, 1, 6), 256, 98304, s2>>>(
        qh, 0, 1, wbh + WQOFF, SMALL, 512,
        nullptr, nullptr, nullptr, 6,
        nullptr, 0, qb, nullptr, nullptr, nullptr, nullptr,
        nullptr, nullptr, nullptr, nullptr, nullptr, nullptr);
    // attention GEMM
    gemm_tc<<<dim3(4, 32, 6), 256, 98304, s2>>>(
        atth, ATTZ, 3, wbh + WKOFF, SMALL, 512,
        nullptr, nullptr, nullptr, 3,
        nullptr, 0, qb, nullptr, nullptr, v_att, upart,
        nullptr, nullptr, nullptr, nullptr, nullptr, nullptr);
    detect_mask_kernel<<<1, 1024, 0, s2>>>((const unsigned int*)kb_mask);
    utk_kernel<<<dim3(KBTOT / 256, BSZ), 256, 0, s2>>>(upart, kb_mask, out_utk);
    cudaEventRecord(evJoin, s2);

    // ---- main: MLP chain ---------------------------------------------------------
    PrepackParams pm;
    pm.d[0] = {arn_w1, arn_w1 + 262144, W1OFF + 0 * BIG, 1024};
    pm.d[1] = {add_w1, add_w1 + 262144, W1OFF + 1 * BIG, 1024};
    pm.d[2] = {wc_w1,  wc_w1  + 262144, W1OFF + 2 * BIG, 1024};
    const float* sw[7] = {arn_w2, arn_w3, add_w2, add_w3, wc_w2, wc_w3, wc_w4};
    for (int j = 0; j < 7; j++)
        pm.d[3 + j] = {sw[j], sw[j], WSOFF2 + j * SMALL, 512};
    for (int j = 10; j < 12; j++) pm.d[j] = pm.d[9];
    prepack_all<<<dim3(32, 16, 10), dim3(32, 8)>>>(pm);

    convert_info<<<8192, 256>>>(x, hidden, ah);
    eng_kernel<<<BT / 8, 256>>>(cell, eng_w, engp);

    // L1: info @ w1 -> h1 hi planes (relu)
    gemm_tc<<<dim3(4, 256, 3), 256, 98304>>>(
        ah, 0, 0, wbh + W1OFF, BIG, 1024,
        arn_b1, add_b1, wc_b1, 0,
        ah + H1_OFF, H1S, nullptr, nullptr, nullptr, nullptr, nullptr,
        nullptr, nullptr, nullptr, nullptr, nullptr, nullptr);
    // L2: h1 @ w2 -> h2 hi planes (relu)
    gemm_tc<<<dim3(4, 256, 3), 256, 98304>>>(
        ah + H1_OFF, H1S, 0, wbh + WSOFF2, 2 * SMALL, 512,
        arn_b2, add_b2, wc_b2, 0,
        ah + H2_OFF, H1S, nullptr, nullptr, nullptr, nullptr, nullptr,
        nullptr, nullptr, nullptr, nullptr, nullptr, nullptr);
    // L3: h2 @ w3; z0 sigmoid->arnh(fp16), z1 tanh->addh(fp16), z2 relu->h3 plane
    gemm_tc<<<dim3(4, 256, 3), 256, 98304>>>(
        ah + H2_OFF, H1S, 0, wbh + WSOFF2 + SMALL, 2 * SMALL, 512,
        arn_b3, add_b3, wc_b3, 5,
        ah + H1_OFF, 0, nullptr, arnh, addh, nullptr, nullptr,
        nullptr, nullptr, nullptr, nullptr, nullptr, nullptr);
    // L4: h3 @ wc_w4 -> fused final epilogue
    gemm_tc<<<dim3(4, 256, 1), 256, 98304>>>(
        ah + H1_OFF, 0, 0, wbh + WSOFF2 + 6 * SMALL, SMALL, 512,
        wc_b4, wc_b4, wc_b4, 4,
        nullptr, 0, nullptr, nullptr, nullptr, nullptr, nullptr,
        arnh, addh, cell, engp, outH, outC);

    // ---- join ---------------------------------------------------------------------
    cudaStreamWaitEvent(0, evJoin, 0);
}

// round 16
// speedup vs baseline: 1.4762x; 1.0067x over previous
#include <cuda_runtime.h>
#include <cuda_fp16.h>
#include <cstdint>

#define HD 512
#define BT 32768
#define BSZ 128
#define KBM 4096
#define KBTOT 32768

typedef unsigned int u32;
typedef unsigned long long u64;
typedef unsigned short u16;

// weight plane slot offsets (elements)
#define BIG    524288ULL                  // 512n x 1024k
#define SMALL  262144ULL                  // 512n x 512k
#define W1OFF  0ULL                       // 3 BIG: arn1, add1, wc1
#define WKOFF  (3ULL*BIG)                 // 6 SMALL Wk
#define WQOFF  (WKOFF + 6ULL*SMALL)       // 6 SMALL Wq
#define WSOFF2 (WQOFF + 6ULL*SMALL)       // 7 SMALL: arn2,arn3,add2,add3,wc2,wc3,wc4
#define WTOT   (WSOFF2 + 7ULL*SMALL)

#define ATTZ   2097152ULL                 // 4096 x 512 per dim
#define H1S    16777216ULL                // 32768 x 512
#define H1_OFF 33554432ULL
#define H2_OFF (H1_OFF + 3*H1S)

__device__ u16   g_wbh[WTOT];
__device__ u16   g_wbl[WTOT];
__device__ u16   g_atth[3*ATTZ];
__device__ u16   g_qh[65536];
__device__ u16   g_ah[134217728];         // hi planes: info + h1[3] + h2[3] (+h3)
__device__ float g_qb[6*128*512];
__device__ u16   g_arnh[(size_t)BT*HD];
__device__ u16   g_addh[(size_t)BT*HD];
__device__ float g_upart[16*6*KBM];
__device__ float g_eng[BT];
__device__ int   g_maskmode;

__device__ __forceinline__ void split2(float v, u16& h, u16& l) {
    __half hh = __float2half_rn(v);
    h = __half_as_ushort(hh);
    l = __half_as_ushort(__float2half_rn(v - __half2float(hh)));
}
__device__ __forceinline__ u32 cvt2(float v0, float v1) {
    u32 r;
    asm("cvt.rn.f16x2.f32 %0, %1, %2;" : "=r"(r) : "f"(v1), "f"(v0));
    return r;
}
__device__ __forceinline__ u32 smem_u32(const void* p) {
    u32 a;
    asm("{ .reg .u64 t; cvta.to.shared.u64 t, %1; cvt.u32.u64 %0, t; }" : "=r"(a) : "l"(p));
    return a;
}
__device__ __forceinline__ void cp16(u32 dst, const void* src) {
    asm volatile("cp.async.cg.shared.global [%0], [%1], 16;" :: "r"(dst), "l"(src));
}
__device__ __forceinline__ void ldsm4(u32* r, u32 a) {
    asm volatile("ldmatrix.sync.aligned.m8n8.x4.shared.b16 {%0,%1,%2,%3}, [%4];"
                 : "=r"(r[0]), "=r"(r[1]), "=r"(r[2]), "=r"(r[3]) : "r"(a));
}
__device__ __forceinline__ void mma16816(float* c, const u32* a, const u32* b) {
    asm volatile("mma.sync.aligned.m16n8k16.row.col.f32.f16.f16.f32 "
                 "{%0,%1,%2,%3},{%4,%5,%6,%7},{%8,%9},{%0,%1,%2,%3};"
                 : "+f"(c[0]), "+f"(c[1]), "+f"(c[2]), "+f"(c[3])
                 : "r"(a[0]), "r"(a[1]), "r"(a[2]), "r"(a[3]), "r"(b[0]), "r"(b[1]));
}

// ---------------- stage loader: k-tile 64, 128B rows, chunk^(row&7) swizzle --
// A-hi @0 (16KB), B-hi @16384; stage stride 32768; 3 stages; 256 threads.
__device__ __forceinline__ void stage_load(
    u32 sb, int slot,
    const u16* __restrict__ Ah, const u16* __restrict__ Bh,
    int mBase, int nBase, int K, int kt, int tid) {
    const u32 so = sb + slot * 32768;
    const int kOff = kt * 64;
#pragma unroll
    for (int j = 0; j < 4; j++) {
        const int id = tid + j * 256;          // 0..1023
        const int r = id >> 3, c = id & 7;
        const u32 dst = so + r * 128 + (((c ^ (r & 7)) & 7) << 4);
        cp16(dst,         Ah + (size_t)(mBase + r) * K + kOff + c * 8);
        cp16(dst + 16384, Bh + (size_t)(nBase + r) * K + kOff + c * 8);
    }
}

// ---------------- GEMM: 128x128 block, 8 warps (64x32 each), 1-term fp16 ----
// modes: 0 relu->hi plane, 3 attention, 4 final fused, 5 L3 combo, 6 raw->plain0
__global__ __launch_bounds__(256, 2)
void gemm_tc(const u16* __restrict__ Ahp, size_t aStrideZ, int aZmod,
             const u16* __restrict__ Bhp, size_t bStrideZ, int K,
             const float* __restrict__ bias0, const float* __restrict__ bias1,
             const float* __restrict__ bias2, int mode,
             u16* __restrict__ oH, size_t oStrideZ,
             float* __restrict__ plain0,
             u16* __restrict__ pH0, u16* __restrict__ pH1,
             const float* __restrict__ vatt, float* __restrict__ upart,
             const u16* __restrict__ p_arnh, const u16* __restrict__ p_addh,
             const float* __restrict__ p_cell, const float* __restrict__ p_eng,
             float* __restrict__ outH, float* __restrict__ outC) {
    extern __shared__ char smem[];
    const u32 sb = smem_u32(smem);
    const int tid = threadIdx.x, lane = tid & 31, warp = tid >> 5;
    const int warpM = warp >> 2, warpN = warp & 3;
    const int rowBase = warpM * 64, colBase = warpN * 32;
    const int nt = blockIdx.x, mt = blockIdx.y, z = blockIdx.z;
    const int mBase = mt * 128, nBase = nt * 128;

    const int az = aZmod ? (z % aZmod) : z;
    const u16* Ah = Ahp + (size_t)az * aStrideZ;
    const u16* Bh = Bhp + (size_t)z * bStrideZ;

    float acc[4][4][4];
#pragma unroll
    for (int i = 0; i < 4; i++)
#pragma unroll
        for (int j = 0; j < 4; j++)
#pragma unroll
            for (int k = 0; k < 4; k++) acc[i][j][k] = 0.0f;

    const int nk = K >> 6;

    stage_load(sb, 0, Ah, Bh, mBase, nBase, K, 0, tid);
    asm volatile("cp.async.commit_group;");
    stage_load(sb, 1, Ah, Bh, mBase, nBase, K, 1, tid);
    asm volatile("cp.async.commit_group;");

    const int arow = (lane & 15);
    const int acb  = (lane >> 4);
    const int brow = (lane & 7) + ((lane >> 4) << 3);
    const int bcb  = (lane >> 3) & 1;

    int slot = 0;
    for (int kt = 0; kt < nk; kt++) {
        if (kt + 1 < nk) asm volatile("cp.async.wait_group 1;");
        else             asm volatile("cp.async.wait_group 0;");
        __syncthreads();
        if (kt + 2 < nk) {
            int ps = slot + 2; if (ps >= 3) ps -= 3;
            stage_load(sb, ps, Ah, Bh, mBase, nBase, K, kt + 2, tid);
            asm volatile("cp.async.commit_group;");
        }
        const u32 so = sb + slot * 32768;
#pragma unroll
        for (int ks = 0; ks < 4; ks++) {
            u32 a_hi[4][4], b_hi[2][4];
#pragma unroll
            for (int mi = 0; mi < 4; mi++) {
                const int r = rowBase + mi * 16 + arow;
                const int c = ks * 2 + acb;
                ldsm4(a_hi[mi], so + r * 128 + (((c ^ (r & 7)) & 7) << 4));
            }
#pragma unroll
            for (int nj = 0; nj < 2; nj++) {
                const int r = colBase + nj * 16 + brow;
                const int c = ks * 2 + bcb;
                ldsm4(b_hi[nj], so + 16384 + r * 128 + (((c ^ (r & 7)) & 7) << 4));
            }
#pragma unroll
            for (int mi = 0; mi < 4; mi++)
#pragma unroll
                for (int ni = 0; ni < 4; ni++)
                    mma16816(acc[mi][ni], a_hi[mi], &b_hi[ni >> 1][(ni & 1) * 2]);
        }
        slot++; if (slot == 3) slot = 0;
    }

    // ---------------- epilogue ----------------
    const float* bias = (z == 0) ? bias0 : (z == 1) ? bias1 : bias2;
    if (mode == 3) {
        const float* qbz = plain0 + (size_t)z * 65536;   // qbias[z][128][512]
#pragma unroll
        for (int mi = 0; mi < 4; mi++) {
#pragma unroll
            for (int h = 0; h < 2; h++) {
                const int m = mBase + rowBase + mi * 16 + (lane >> 2) + h * 8;
                const float* qrow = qbz + (size_t)(m >> 5) * 512;
                float s = 0.0f;
#pragma unroll
                for (int ni = 0; ni < 4; ni++) {
                    const int n = nBase + colBase + ni * 8 + (lane & 3) * 2;
                    const float2 qv = *(const float2*)&qrow[n];
                    s += tanhf(acc[mi][ni][h * 2]     + qv.x) * vatt[z * 512 + n];
                    s += tanhf(acc[mi][ni][h * 2 + 1] + qv.y) * vatt[z * 512 + n + 1];
                }
                s += __shfl_xor_sync(0xffffffffu, s, 1);
                s += __shfl_xor_sync(0xffffffffu, s, 2);
                if ((lane & 3) == 0)
                    upart[((size_t)(nt * 4 + warpN) * 6 + z) * KBM + m] = s;
            }
        }
        return;
    }
#pragma unroll
    for (int mi = 0; mi < 4; mi++) {
#pragma unroll
        for (int h = 0; h < 2; h++) {
            const int m = mBase + rowBase + mi * 16 + (lane >> 2) + h * 8;
#pragma unroll
            for (int ni = 0; ni < 4; ni++) {
                const int n = nBase + colBase + ni * 8 + (lane & 3) * 2;
                float v0 = acc[mi][ni][h * 2];
                float v1 = acc[mi][ni][h * 2 + 1];
                if (mode != 6) { v0 += bias[n]; v1 += bias[n + 1]; }
                const size_t i0 = (size_t)m * 512 + n;
                if (mode == 6) {
                    *(float2*)&plain0[(size_t)z * 65536 + i0] = make_float2(v0, v1);
                } else if (mode == 4) {
                    const float e = p_eng[m];
                    const float wc0 = 1.0f / (1.0f + expf(-v0));
                    const float wc1 = 1.0f / (1.0f + expf(-v1));
                    const float2 cc = *(const float2*)&p_cell[i0];
                    const float2 aa = __half22float2(*(const __half2*)&p_arnh[i0]);
                    const float2 dd = __half22float2(*(const __half2*)&p_addh[i0]);
                    const float uc0 = cc.x + aa.x * dd.x * e;
                    const float uc1 = cc.y + aa.y * dd.y * e;
                    *(float2*)&outC[i0] = make_float2(uc0, uc1);
                    *(float2*)&outH[i0] = make_float2(wc0 * tanhf(uc0), wc1 * tanhf(uc1));
                } else if (mode == 5 && z < 2) {
                    u16* pl = (z == 0) ? pH0 : pH1;
                    if (z == 0) { v0 = 1.0f / (1.0f + expf(-v0)); v1 = 1.0f / (1.0f + expf(-v1)); }
                    else        { v0 = tanhf(v0); v1 = tanhf(v1); }
                    *(u32*)&pl[i0] = cvt2(v0, v1);
                } else {
                    v0 = fmaxf(v0, 0.0f); v1 = fmaxf(v1, 0.0f);
                    u16* dH = oH + (mode == 5 ? 0 : (size_t)z * oStrideZ);
                    *(u32*)&dH[i0] = cvt2(v0, v1);
                }
            }
        }
    }
}

// ---------------- merged weight prepack ---------------------------------------
struct PrepackDesc { const float* s0; const float* s1; size_t off; int K; };
struct PrepackParams { PrepackDesc d[12]; };

__global__ void prepack_all(PrepackParams p) {
    __shared__ float t[32][33];
    const PrepackDesc de = p.d[blockIdx.z];
    const int K = de.K;
    const int k0 = blockIdx.x * 32;
    if (k0 >= K) return;
    const int n0 = blockIdx.y * 32;
    const int tx = threadIdx.x, ty = threadIdx.y;
#pragma unroll
    for (int i = 0; i < 4; i++) {
        const int k = k0 + ty + i * 8;
        t[ty + i * 8][tx] = (k < 512) ? de.s0[(size_t)k * 512 + n0 + tx]
                                      : de.s1[(size_t)(k - 512) * 512 + n0 + tx];
    }
    __syncthreads();
#pragma unroll
    for (int i = 0; i < 4; i++) {
        const int n = n0 + ty + i * 8;
        const int k = k0 + tx;
        u16 h, l; split2(t[tx][ty + i * 8], h, l);
        g_wbh[de.off + (size_t)n * K + k] = h;
        g_wbl[de.off + (size_t)n * K + k] = l;
    }
}

// ---------------- activation converters (MLP=4, coalesced) --------------------
// one block = 4 rows; thread t handles float4 #t of each row (coalesced per row)
__global__ void convert_info(const float* __restrict__ x, const float* __restrict__ h,
                             u16* __restrict__ dh) {
    const int t = threadIdx.x;          // 0..255, float4 index within 1024-float row
    const int k = t << 2;
    const int m0 = blockIdx.x << 2;
    const float* src = (k < 512) ? (x + k) : (h + k - 512);
    float4 v[4];
#pragma unroll
    for (int r = 0; r < 4; r++)
        v[r] = *(const float4*)(src + (size_t)(m0 + r) * 512);
#pragma unroll
    for (int r = 0; r < 4; r++) {
        const u64 hw = (u64)cvt2(v[r].x, v[r].y) | ((u64)cvt2(v[r].z, v[r].w) << 32);
        *(u64*)&dh[(size_t)(m0 + r) * 1024 + k] = hw;
    }
}
__global__ void convert_att(const float* __restrict__ kbk, const float* __restrict__ q) {
    const int y = blockIdx.y;
    const int t = threadIdx.x;          // 0..127, float4 index within 512-float row
    const int k = t << 2;
    const int m0 = blockIdx.x << 2;
    const float* src;
    u16* dh;
    if (y < 3) {
        src = kbk + (size_t)y * 4096 * 512 + k;
        dh = g_atth + (size_t)y * ATTZ;
    } else {
        if (m0 >= 128) return;
        src = q + k;
        dh = g_qh;
    }
    float4 v[4];
#pragma unroll
    for (int r = 0; r < 4; r++)
        v[r] = *(const float4*)(src + (size_t)(m0 + r) * 512);
#pragma unroll
    for (int r = 0; r < 4; r++) {
        const u64 hw = (u64)cvt2(v[r].x, v[r].y) | ((u64)cvt2(v[r].z, v[r].w) << 32);
        *(u64*)&dh[(size_t)(m0 + r) * 512 + k] = hw;
    }
}

// ---------------- small kernels -------------------------------------------------
__global__ void eng_kernel(const float* __restrict__ cell, const float* __restrict__ w,
                           float* __restrict__ eng) {
    const int row = blockIdx.x * 8 + (threadIdx.x >> 5);
    const int lane = threadIdx.x & 31;
    const float* c = cell + (size_t)row * HD;
    float s = 0.0f;
#pragma unroll 4
    for (int k = lane; k < HD; k += 32) s += c[k] * w[k];
#pragma unroll
    for (int o = 16; o; o >>= 1) s += __shfl_down_sync(0xffffffffu, s, o);
    if (!lane) eng[row] = s;
}
__global__ void detect_mask_kernel(const unsigned int* __restrict__ w) {
    __shared__ int sF, sG;
    if (threadIdx.x == 0) { sF = 0; sG = 0; }
    __syncthreads();
    int f = 0, g = 0;
    for (int i = threadIdx.x; i < 65536; i += blockDim.x) {
        const unsigned int v = w[i];
        if (v == 0x3F800000u) f = 1;
        else if (v > 1u) g = 1;
    }
    if (f) atomicOr(&sF, 1);
    if (g) atomicOr(&sG, 1);
    __syncthreads();
    if (threadIdx.x == 0) g_maskmode = sF ? 2 : (sG ? 0 : 1);
}
__global__ void utk_kernel(const float* __restrict__ up, const void* __restrict__ maskraw,
                           float* __restrict__ out) {
    __shared__ float S[3][32];
    const int b = blockIdx.y;
    if (threadIdx.x < 96) {
        const int d = threadIdx.x >> 5, i = threadIdx.x & 31;
        float s = 0.0f;
#pragma unroll
        for (int p = 0; p < 16; p++)
#pragma unroll
            for (int hop = 0; hop < 2; hop++)
                s += up[((size_t)p * 6 + hop * 3 + d) * KBM + b * 32 + i];
        S[d][i] = s;
    }
    __syncthreads();
    const int mode = g_maskmode;
    const int j = blockIdx.x * 256 + threadIdx.x;
    const float v = S[0][j >> 10] + S[1][(j >> 5) & 31] + S[2][j & 31];
    const size_t o = (size_t)b * KBTOT + j;
    bool msk;
    if (mode == 0)      msk = ((const unsigned char*)maskraw)[o] != 0;
    else if (mode == 1) msk = ((const int*)maskraw)[o] != 0;
    else                msk = ((const float*)maskraw)[o] != 0.0f;
    out[o] = msk ? 0.0f : v;
}

// ---------------- host -----------------------------------------------------------
extern "C" void kernel_launch(void* const* d_in, const int* in_sizes, int n_in,
                              void* d_out, int out_size) {
    const float* query   = (const float*)d_in[0];
    const float* kb_keys = (const float*)d_in[1];
    const float* Wq      = (const float*)d_in[2];
    const float* Wk      = (const float*)d_in[3];
    const float* v_att   = (const float*)d_in[4];
    const float* x       = (const float*)d_in[5];
    const float* hidden  = (const float*)d_in[6];
    const float* cell    = (const float*)d_in[7];
    const float* arn_w1  = (const float*)d_in[8];
    const float* arn_b1  = (const float*)d_in[9];
    const float* arn_w2  = (const float*)d_in[10];
    const float* arn_b2  = (const float*)d_in[11];
    const float* arn_w3  = (const float*)d_in[12];
    const float* arn_b3  = (const float*)d_in[13];
    const float* add_w1  = (const float*)d_in[14];
    const float* add_b1  = (const float*)d_in[15];
    const float* add_w2  = (const float*)d_in[16];
    const float* add_b2  = (const float*)d_in[17];
    const float* add_w3  = (const float*)d_in[18];
    const float* add_b3  = (const float*)d_in[19];
    const float* eng_w   = (const float*)d_in[20];
    const float* wc_w1   = (const float*)d_in[21];
    const float* wc_b1   = (const float*)d_in[22];
    const float* wc_w2   = (const float*)d_in[23];
    const float* wc_b2   = (const float*)d_in[24];
    const float* wc_w3   = (const float*)d_in[25];
    const float* wc_b3   = (const float*)d_in[26];
    const float* wc_w4   = (const float*)d_in[27];
    const float* wc_b4   = (const float*)d_in[28];
    const void*  kb_mask = d_in[29];

    float* out     = (float*)d_out;
    float* out_utk = out;
    float* outH    = out + (size_t)BSZ * KBTOT;
    float* outC    = outH + (size_t)BT * HD;

    u16 *wbh, *atth, *qh, *ah, *arnh, *addh;
    float *qb, *upart, *engp;
    cudaGetSymbolAddress((void**)&wbh,  g_wbh);
    cudaGetSymbolAddress((void**)&atth, g_atth);
    cudaGetSymbolAddress((void**)&qh,   g_qh);
    cudaGetSymbolAddress((void**)&ah,   g_ah);
    cudaGetSymbolAddress((void**)&arnh, g_arnh);
    cudaGetSymbolAddress((void**)&addh, g_addh);
    cudaGetSymbolAddress((void**)&qb,   g_qb);
    cudaGetSymbolAddress((void**)&upart,g_upart);
    cudaGetSymbolAddress((void**)&engp, g_eng);

    static cudaStream_t s2 = nullptr, s3 = nullptr;
    static cudaEvent_t evFork = nullptr, evJoin = nullptr, evJoin3 = nullptr;
    if (!s2) {
        cudaFuncSetAttribute(gemm_tc, cudaFuncAttributeMaxDynamicSharedMemorySize, 98304);
        cudaStreamCreateWithFlags(&s2, cudaStreamNonBlocking);
        cudaStreamCreateWithFlags(&s3, cudaStreamNonBlocking);
        cudaEventCreateWithFlags(&evFork, cudaEventDisableTiming);
        cudaEventCreateWithFlags(&evJoin, cudaEventDisableTiming);
        cudaEventCreateWithFlags(&evJoin3, cudaEventDisableTiming);
    }

    // ---- fork immediately ----------------------------------------------------------
    cudaEventRecord(evFork, 0);
    cudaStreamWaitEvent(s2, evFork, 0);
    cudaStreamWaitEvent(s3, evFork, 0);

    // s2: attention chain (unchanged)
    PrepackParams pa;
    for (int i = 0; i < 6; i++) {
        pa.d[i]     = {Wk + (size_t)i * 262144, Wk + (size_t)i * 262144, WKOFF + i * SMALL, 512};
        pa.d[6 + i] = {Wq + (size_t)i * 262144, Wq + (size_t)i * 262144, WQOFF + i * SMALL, 512};
    }
    prepack_all<<<dim3(16, 16, 12), dim3(32, 8), 0, s2>>>(pa);
    convert_att<<<dim3(1024, 4), 128, 0, s2>>>(kb_keys, query);
    gemm_tc<<<dim3(4, 1, 6), 256, 98304, s2>>>(
        qh, 0, 1, wbh + WQOFF, SMALL, 512,
        nullptr, nullptr, nullptr, 6,
        nullptr, 0, qb, nullptr, nullptr, nullptr, nullptr,
        nullptr, nullptr, nullptr, nullptr, nullptr, nullptr);
    gemm_tc<<<dim3(4, 32, 6), 256, 98304, s2>>>(
        atth, ATTZ, 3, wbh + WKOFF, SMALL, 512,
        nullptr, nullptr, nullptr, 3,
        nullptr, 0, qb, nullptr, nullptr, v_att, upart,
        nullptr, nullptr, nullptr, nullptr, nullptr, nullptr);
    detect_mask_kernel<<<1, 1024, 0, s2>>>((const unsigned int*)kb_mask);
    utk_kernel<<<dim3(KBTOT / 256, BSZ), 256, 0, s2>>>(upart, kb_mask, out_utk);
    cudaEventRecord(evJoin, s2);

    // s3: coalesced converters + eng, overlapping MLP prepack on main
    convert_info<<<8192, 256, 0, s3>>>(x, hidden, ah);
    eng_kernel<<<BT / 8, 256, 0, s3>>>(cell, eng_w, engp);
    cudaEventRecord(evJoin3, s3);

    // main: MLP weight prepack
    PrepackParams pm;
    pm.d[0] = {arn_w1, arn_w1 + 262144, W1OFF + 0 * BIG, 1024};
    pm.d[1] = {add_w1, add_w1 + 262144, W1OFF + 1 * BIG, 1024};
    pm.d[2] = {wc_w1,  wc_w1  + 262144, W1OFF + 2 * BIG, 1024};
    const float* sw[7] = {arn_w2, arn_w3, add_w2, add_w3, wc_w2, wc_w3, wc_w4};
    for (int j = 0; j < 7; j++)
        pm.d[3 + j] = {sw[j], sw[j], WSOFF2 + j * SMALL, 512};
    for (int j = 10; j < 12; j++) pm.d[j] = pm.d[9];
    prepack_all<<<dim3(32, 16, 10), dim3(32, 8)>>>(pm);
    cudaStreamWaitEvent(0, evJoin3, 0);

    // L1: info @ w1 -> h1 hi planes (relu)
    gemm_tc<<<dim3(4, 256, 3), 256, 98304>>>(
        ah, 0, 0, wbh + W1OFF, BIG, 1024,
        arn_b1, add_b1, wc_b1, 0,
        ah + H1_OFF, H1S, nullptr, nullptr, nullptr, nullptr, nullptr,
        nullptr, nullptr, nullptr, nullptr, nullptr, nullptr);
    // L2: h1 @ w2 -> h2 hi planes (relu)
    gemm_tc<<<dim3(4, 256, 3), 256, 98304>>>(
        ah + H1_OFF, H1S, 0, wbh + WSOFF2, 2 * SMALL, 512,
        arn_b2, add_b2, wc_b2, 0,
        ah + H2_OFF, H1S, nullptr, nullptr, nullptr, nullptr, nullptr,
        nullptr, nullptr, nullptr, nullptr, nullptr, nullptr);
    // L3: h2 @ w3; z0 sigmoid->arnh(fp16), z1 tanh->addh(fp16), z2 relu->h3 plane
    gemm_tc<<<dim3(4, 256, 3), 256, 98304>>>(
        ah + H2_OFF, H1S, 0, wbh + WSOFF2 + SMALL, 2 * SMALL, 512,
        arn_b3, add_b3, wc_b3, 5,
        ah + H1_OFF, 0, nullptr, arnh, addh, nullptr, nullptr,
        nullptr, nullptr, nullptr, nullptr, nullptr, nullptr);
    // L4: h3 @ wc_w4 -> fused final epilogue
    gemm_tc<<<dim3(4, 256, 1), 256, 98304>>>(
        ah + H1_OFF, 0, 0, wbh + WSOFF2 + 6 * SMALL, SMALL, 512,
        wc_b4, wc_b4, wc_b4, 4,
        nullptr, 0, nullptr, nullptr, nullptr, nullptr, nullptr,
        arnh, addh, cell, engp, outH, outC);

    // ---- join -----------------------------------------------------------------------
    cudaStreamWaitEvent(0, evJoin, 0);
}

// round 17
// speedup vs baseline: 1.4799x; 1.0025x over previous
#include <cuda_runtime.h>
#include <cuda_fp16.h>
#include <cstdint>

#define HD 512
#define BT 32768
#define BSZ 128
#define KBM 4096
#define KBTOT 32768

typedef unsigned int u32;
typedef unsigned long long u64;
typedef unsigned short u16;

// weight plane slot offsets (elements)
#define BIG    524288ULL                  // 512n x 1024k
#define SMALL  262144ULL                  // 512n x 512k
#define W1OFF  0ULL                       // 3 BIG: arn1, add1, wc1
#define WKOFF  (3ULL*BIG)                 // 6 SMALL Wk
#define WQOFF  (WKOFF + 6ULL*SMALL)       // 6 SMALL Wq
#define WSOFF2 (WQOFF + 6ULL*SMALL)       // 7 SMALL: arn2,arn3,add2,add3,wc2,wc3,wc4
#define WTOT   (WSOFF2 + 7ULL*SMALL)

#define ATTZ   2097152ULL                 // 4096 x 512 per dim
#define H1S    16777216ULL                // 32768 x 512
#define H1_OFF 33554432ULL
#define H2_OFF (H1_OFF + 3*H1S)

__device__ u16   g_wbh[WTOT];
__device__ u16   g_atth[3*ATTZ];
__device__ u16   g_qh[65536];
__device__ u16   g_ah[134217728];         // hi planes: info + h1[3] + h2[3] (+h3)
__device__ float g_qb[6*128*512];
__device__ u16   g_arnh[(size_t)BT*HD];
__device__ u16   g_addh[(size_t)BT*HD];
__device__ float g_upart[16*6*KBM];
__device__ float g_eng[BT];
__device__ int   g_maskmode;

__device__ __forceinline__ u32 cvt2(float v0, float v1) {
    u32 r;
    asm("cvt.rn.f16x2.f32 %0, %1, %2;" : "=r"(r) : "f"(v1), "f"(v0));
    return r;
}
__device__ __forceinline__ u32 smem_u32(const void* p) {
    u32 a;
    asm("{ .reg .u64 t; cvta.to.shared.u64 t, %1; cvt.u32.u64 %0, t; }" : "=r"(a) : "l"(p));
    return a;
}
__device__ __forceinline__ void cp16(u32 dst, const void* src) {
    asm volatile("cp.async.cg.shared.global [%0], [%1], 16;" :: "r"(dst), "l"(src));
}
__device__ __forceinline__ void ldsm4(u32* r, u32 a) {
    asm volatile("ldmatrix.sync.aligned.m8n8.x4.shared.b16 {%0,%1,%2,%3}, [%4];"
                 : "=r"(r[0]), "=r"(r[1]), "=r"(r[2]), "=r"(r[3]) : "r"(a));
}
__device__ __forceinline__ void mma16816(float* c, const u32* a, const u32* b) {
    asm volatile("mma.sync.aligned.m16n8k16.row.col.f32.f16.f16.f32 "
                 "{%0,%1,%2,%3},{%4,%5,%6,%7},{%8,%9},{%0,%1,%2,%3};"
                 : "+f"(c[0]), "+f"(c[1]), "+f"(c[2]), "+f"(c[3])
                 : "r"(a[0]), "r"(a[1]), "r"(a[2]), "r"(a[3]), "r"(b[0]), "r"(b[1]));
}

// ---------------- stage loader: k-tile 64, 128B rows, chunk^(row&7) swizzle --
// A-hi @0 (16KB), B-hi @16384; stage stride 32768; 3 stages; 256 threads.
__device__ __forceinline__ void stage_load(
    u32 sb, int slot,
    const u16* __restrict__ Ah, const u16* __restrict__ Bh,
    int mBase, int nBase, int K, int kt, int tid) {
    const u32 so = sb + slot * 32768;
    const int kOff = kt * 64;
#pragma unroll
    for (int j = 0; j < 4; j++) {
        const int id = tid + j * 256;          // 0..1023
        const int r = id >> 3, c = id & 7;
        const u32 dst = so + r * 128 + (((c ^ (r & 7)) & 7) << 4);
        cp16(dst,         Ah + (size_t)(mBase + r) * K + kOff + c * 8);
        cp16(dst + 16384, Bh + (size_t)(nBase + r) * K + kOff + c * 8);
    }
}

// ---------------- GEMM: 128x128 block, 8 warps (64x32 each), 1-term fp16 ----
// modes: 0 relu->hi plane, 3 attention, 4 final fused, 5 L3 combo, 6 raw->plain0
__global__ __launch_bounds__(256, 2)
void gemm_tc(const u16* __restrict__ Ahp, size_t aStrideZ, int aZmod,
             const u16* __restrict__ Bhp, size_t bStrideZ, int K,
             const float* __restrict__ bias0, const float* __restrict__ bias1,
             const float* __restrict__ bias2, int mode,
             u16* __restrict__ oH, size_t oStrideZ,
             float* __restrict__ plain0,
             u16* __restrict__ pH0, u16* __restrict__ pH1,
             const float* __restrict__ vatt, float* __restrict__ upart,
             const u16* __restrict__ p_arnh, const u16* __restrict__ p_addh,
             const float* __restrict__ p_cell, const float* __restrict__ p_eng,
             float* __restrict__ outH, float* __restrict__ outC) {
    extern __shared__ char smem[];
    const u32 sb = smem_u32(smem);
    const int tid = threadIdx.x, lane = tid & 31, warp = tid >> 5;
    const int warpM = warp >> 2, warpN = warp & 3;
    const int rowBase = warpM * 64, colBase = warpN * 32;
    const int nt = blockIdx.x, mt = blockIdx.y, z = blockIdx.z;
    const int mBase = mt * 128, nBase = nt * 128;

    const int az = aZmod ? (z % aZmod) : z;
    const u16* Ah = Ahp + (size_t)az * aStrideZ;
    const u16* Bh = Bhp + (size_t)z * bStrideZ;

    float acc[4][4][4];
#pragma unroll
    for (int i = 0; i < 4; i++)
#pragma unroll
        for (int j = 0; j < 4; j++)
#pragma unroll
            for (int k = 0; k < 4; k++) acc[i][j][k] = 0.0f;

    const int nk = K >> 6;

    stage_load(sb, 0, Ah, Bh, mBase, nBase, K, 0, tid);
    asm volatile("cp.async.commit_group;");
    stage_load(sb, 1, Ah, Bh, mBase, nBase, K, 1, tid);
    asm volatile("cp.async.commit_group;");

    const int arow = (lane & 15);
    const int acb  = (lane >> 4);
    const int brow = (lane & 7) + ((lane >> 4) << 3);
    const int bcb  = (lane >> 3) & 1;

    int slot = 0;
    for (int kt = 0; kt < nk; kt++) {
        if (kt + 1 < nk) asm volatile("cp.async.wait_group 1;");
        else             asm volatile("cp.async.wait_group 0;");
        __syncthreads();
        if (kt + 2 < nk) {
            int ps = slot + 2; if (ps >= 3) ps -= 3;
            stage_load(sb, ps, Ah, Bh, mBase, nBase, K, kt + 2, tid);
            asm volatile("cp.async.commit_group;");
        }
        const u32 so = sb + slot * 32768;
#pragma unroll
        for (int ks = 0; ks < 4; ks++) {
            u32 a_hi[4][4], b_hi[2][4];
#pragma unroll
            for (int mi = 0; mi < 4; mi++) {
                const int r = rowBase + mi * 16 + arow;
                const int c = ks * 2 + acb;
                ldsm4(a_hi[mi], so + r * 128 + (((c ^ (r & 7)) & 7) << 4));
            }
#pragma unroll
            for (int nj = 0; nj < 2; nj++) {
                const int r = colBase + nj * 16 + brow;
                const int c = ks * 2 + bcb;
                ldsm4(b_hi[nj], so + 16384 + r * 128 + (((c ^ (r & 7)) & 7) << 4));
            }
#pragma unroll
            for (int mi = 0; mi < 4; mi++)
#pragma unroll
                for (int ni = 0; ni < 4; ni++)
                    mma16816(acc[mi][ni], a_hi[mi], &b_hi[ni >> 1][(ni & 1) * 2]);
        }
        slot++; if (slot == 3) slot = 0;
    }

    // ---------------- epilogue ----------------
    const float* bias = (z == 0) ? bias0 : (z == 1) ? bias1 : bias2;
    if (mode == 3) {
        const float* qbz = plain0 + (size_t)z * 65536;   // qbias[z][128][512]
#pragma unroll
        for (int mi = 0; mi < 4; mi++) {
#pragma unroll
            for (int h = 0; h < 2; h++) {
                const int m = mBase + rowBase + mi * 16 + (lane >> 2) + h * 8;
                const float* qrow = qbz + (size_t)(m >> 5) * 512;
                float s = 0.0f;
#pragma unroll
                for (int ni = 0; ni < 4; ni++) {
                    const int n = nBase + colBase + ni * 8 + (lane & 3) * 2;
                    const float2 qv = *(const float2*)&qrow[n];
                    s += tanhf(acc[mi][ni][h * 2]     + qv.x) * vatt[z * 512 + n];
                    s += tanhf(acc[mi][ni][h * 2 + 1] + qv.y) * vatt[z * 512 + n + 1];
                }
                s += __shfl_xor_sync(0xffffffffu, s, 1);
                s += __shfl_xor_sync(0xffffffffu, s, 2);
                if ((lane & 3) == 0)
                    upart[((size_t)(nt * 4 + warpN) * 6 + z) * KBM + m] = s;
            }
        }
        return;
    }
#pragma unroll
    for (int mi = 0; mi < 4; mi++) {
#pragma unroll
        for (int h = 0; h < 2; h++) {
            const int m = mBase + rowBase + mi * 16 + (lane >> 2) + h * 8;
#pragma unroll
            for (int ni = 0; ni < 4; ni++) {
                const int n = nBase + colBase + ni * 8 + (lane & 3) * 2;
                float v0 = acc[mi][ni][h * 2];
                float v1 = acc[mi][ni][h * 2 + 1];
                if (mode != 6) { v0 += bias[n]; v1 += bias[n + 1]; }
                const size_t i0 = (size_t)m * 512 + n;
                if (mode == 6) {
                    *(float2*)&plain0[(size_t)z * 65536 + i0] = make_float2(v0, v1);
                } else if (mode == 4) {
                    const float e = p_eng[m];
                    const float wc0 = 1.0f / (1.0f + expf(-v0));
                    const float wc1 = 1.0f / (1.0f + expf(-v1));
                    const float2 cc = *(const float2*)&p_cell[i0];
                    const float2 aa = __half22float2(*(const __half2*)&p_arnh[i0]);
                    const float2 dd = __half22float2(*(const __half2*)&p_addh[i0]);
                    const float uc0 = cc.x + aa.x * dd.x * e;
                    const float uc1 = cc.y + aa.y * dd.y * e;
                    *(float2*)&outC[i0] = make_float2(uc0, uc1);
                    *(float2*)&outH[i0] = make_float2(wc0 * tanhf(uc0), wc1 * tanhf(uc1));
                } else if (mode == 5 && z < 2) {
                    u16* pl = (z == 0) ? pH0 : pH1;
                    if (z == 0) { v0 = 1.0f / (1.0f + expf(-v0)); v1 = 1.0f / (1.0f + expf(-v1)); }
                    else        { v0 = tanhf(v0); v1 = tanhf(v1); }
                    *(u32*)&pl[i0] = cvt2(v0, v1);
                } else {
                    v0 = fmaxf(v0, 0.0f); v1 = fmaxf(v1, 0.0f);
                    u16* dH = oH + (mode == 5 ? 0 : (size_t)z * oStrideZ);
                    *(u32*)&dH[i0] = cvt2(v0, v1);
                }
            }
        }
    }
}

// ---------------- merged weight prepack (hi plane only) ------------------------
struct PrepackDesc { const float* s0; const float* s1; size_t off; int K; };
struct PrepackParams { PrepackDesc d[12]; };

__global__ void prepack_all(PrepackParams p) {
    __shared__ float t[32][33];
    const PrepackDesc de = p.d[blockIdx.z];
    const int K = de.K;
    const int k0 = blockIdx.x * 32;
    if (k0 >= K) return;
    const int n0 = blockIdx.y * 32;
    const int tx = threadIdx.x, ty = threadIdx.y;
#pragma unroll
    for (int i = 0; i < 4; i++) {
        const int k = k0 + ty + i * 8;
        t[ty + i * 8][tx] = (k < 512) ? de.s0[(size_t)k * 512 + n0 + tx]
                                      : de.s1[(size_t)(k - 512) * 512 + n0 + tx];
    }
    __syncthreads();
#pragma unroll
    for (int i = 0; i < 4; i++) {
        const int n = n0 + ty + i * 8;
        const int k = k0 + tx;
        g_wbh[de.off + (size_t)n * K + k] =
            __half_as_ushort(__float2half_rn(t[tx][ty + i * 8]));
    }
}

// ---------------- activation converters (MLP=4, coalesced) --------------------
__global__ void convert_info(const float* __restrict__ x, const float* __restrict__ h,
                             u16* __restrict__ dh) {
    const int t = threadIdx.x;          // 0..255, float4 index within 1024-float row
    const int k = t << 2;
    const int m0 = blockIdx.x << 2;
    const float* src = (k < 512) ? (x + k) : (h + k - 512);
    float4 v[4];
#pragma unroll
    for (int r = 0; r < 4; r++)
        v[r] = *(const float4*)(src + (size_t)(m0 + r) * 512);
#pragma unroll
    for (int r = 0; r < 4; r++) {
        const u64 hw = (u64)cvt2(v[r].x, v[r].y) | ((u64)cvt2(v[r].z, v[r].w) << 32);
        *(u64*)&dh[(size_t)(m0 + r) * 1024 + k] = hw;
    }
}
__global__ void convert_att(const float* __restrict__ kbk, const float* __restrict__ q) {
    const int y = blockIdx.y;
    const int t = threadIdx.x;          // 0..127, float4 index within 512-float row
    const int k = t << 2;
    const int m0 = blockIdx.x << 2;
    const float* src;
    u16* dh;
    if (y < 3) {
        src = kbk + (size_t)y * 4096 * 512 + k;
        dh = g_atth + (size_t)y * ATTZ;
    } else {
        if (m0 >= 128) return;
        src = q + k;
        dh = g_qh;
    }
    float4 v[4];
#pragma unroll
    for (int r = 0; r < 4; r++)
        v[r] = *(const float4*)(src + (size_t)(m0 + r) * 512);
#pragma unroll
    for (int r = 0; r < 4; r++) {
        const u64 hw = (u64)cvt2(v[r].x, v[r].y) | ((u64)cvt2(v[r].z, v[r].w) << 32);
        *(u64*)&dh[(size_t)(m0 + r) * 512 + k] = hw;
    }
}

// ---------------- small kernels -------------------------------------------------
__global__ void eng_kernel(const float* __restrict__ cell, const float* __restrict__ w,
                           float* __restrict__ eng) {
    const int row = blockIdx.x * 8 + (threadIdx.x >> 5);
    const int lane = threadIdx.x & 31;
    const float* c = cell + (size_t)row * HD;
    float s = 0.0f;
#pragma unroll 4
    for (int k = lane; k < HD; k += 32) s += c[k] * w[k];
#pragma unroll
    for (int o = 16; o; o >>= 1) s += __shfl_down_sync(0xffffffffu, s, o);
    if (!lane) eng[row] = s;
}
__global__ void detect_mask_kernel(const unsigned int* __restrict__ w) {
    __shared__ int sF, sG;
    if (threadIdx.x == 0) { sF = 0; sG = 0; }
    __syncthreads();
    int f = 0, g = 0;
    for (int i = threadIdx.x; i < 65536; i += blockDim.x) {
        const unsigned int v = w[i];
        if (v == 0x3F800000u) f = 1;
        else if (v > 1u) g = 1;
    }
    if (f) atomicOr(&sF, 1);
    if (g) atomicOr(&sG, 1);
    __syncthreads();
    if (threadIdx.x == 0) g_maskmode = sF ? 2 : (sG ? 0 : 1);
}
__global__ void utk_kernel(const float* __restrict__ up, const void* __restrict__ maskraw,
                           float* __restrict__ out) {
    __shared__ float S[3][32];
    const int b = blockIdx.y;
    if (threadIdx.x < 96) {
        const int d = threadIdx.x >> 5, i = threadIdx.x & 31;
        float s = 0.0f;
#pragma unroll
        for (int p = 0; p < 16; p++)
#pragma unroll
            for (int hop = 0; hop < 2; hop++)
                s += up[((size_t)p * 6 + hop * 3 + d) * KBM + b * 32 + i];
        S[d][i] = s;
    }
    __syncthreads();
    const int mode = g_maskmode;
    const int j = blockIdx.x * 256 + threadIdx.x;
    const float v = S[0][j >> 10] + S[1][(j >> 5) & 31] + S[2][j & 31];
    const size_t o = (size_t)b * KBTOT + j;
    bool msk;
    if (mode == 0)      msk = ((const unsigned char*)maskraw)[o] != 0;
    else if (mode == 1) msk = ((const int*)maskraw)[o] != 0;
    else                msk = ((const float*)maskraw)[o] != 0.0f;
    out[o] = msk ? 0.0f : v;
}

// ---------------- host -----------------------------------------------------------
extern "C" void kernel_launch(void* const* d_in, const int* in_sizes, int n_in,
                              void* d_out, int out_size) {
    const float* query   = (const float*)d_in[0];
    const float* kb_keys = (const float*)d_in[1];
    const float* Wq      = (const float*)d_in[2];
    const float* Wk      = (const float*)d_in[3];
    const float* v_att   = (const float*)d_in[4];
    const float* x       = (const float*)d_in[5];
    const float* hidden  = (const float*)d_in[6];
    const float* cell    = (const float*)d_in[7];
    const float* arn_w1  = (const float*)d_in[8];
    const float* arn_b1  = (const float*)d_in[9];
    const float* arn_w2  = (const float*)d_in[10];
    const float* arn_b2  = (const float*)d_in[11];
    const float* arn_w3  = (const float*)d_in[12];
    const float* arn_b3  = (const float*)d_in[13];
    const float* add_w1  = (const float*)d_in[14];
    const float* add_b1  = (const float*)d_in[15];
    const float* add_w2  = (const float*)d_in[16];
    const float* add_b2  = (const float*)d_in[17];
    const float* add_w3  = (const float*)d_in[18];
    const float* add_b3  = (const float*)d_in[19];
    const float* eng_w   = (const float*)d_in[20];
    const float* wc_w1   = (const float*)d_in[21];
    const float* wc_b1   = (const float*)d_in[22];
    const float* wc_w2   = (const float*)d_in[23];
    const float* wc_b2   = (const float*)d_in[24];
    const float* wc_w3   = (const float*)d_in[25];
    const float* wc_b3   = (const float*)d_in[26];
    const float* wc_w4   = (const float*)d_in[27];
    const float* wc_b4   = (const float*)d_in[28];
    const void*  kb_mask = d_in[29];

    float* out     = (float*)d_out;
    float* out_utk = out;
    float* outH    = out + (size_t)BSZ * KBTOT;
    float* outC    = outH + (size_t)BT * HD;

    u16 *wbh, *atth, *qh, *ah, *arnh, *addh;
    float *qb, *upart, *engp;
    cudaGetSymbolAddress((void**)&wbh,  g_wbh);
    cudaGetSymbolAddress((void**)&atth, g_atth);
    cudaGetSymbolAddress((void**)&qh,   g_qh);
    cudaGetSymbolAddress((void**)&ah,   g_ah);
    cudaGetSymbolAddress((void**)&arnh, g_arnh);
    cudaGetSymbolAddress((void**)&addh, g_addh);
    cudaGetSymbolAddress((void**)&qb,   g_qb);
    cudaGetSymbolAddress((void**)&upart,g_upart);
    cudaGetSymbolAddress((void**)&engp, g_eng);

    static cudaStream_t s2 = nullptr, s3 = nullptr;
    static cudaEvent_t evFork = nullptr, evJoin = nullptr, evJoin3 = nullptr;
    if (!s2) {
        cudaFuncSetAttribute(gemm_tc, cudaFuncAttributeMaxDynamicSharedMemorySize, 98304);
        cudaStreamCreateWithFlags(&s2, cudaStreamNonBlocking);
        cudaStreamCreateWithFlags(&s3, cudaStreamNonBlocking);
        cudaEventCreateWithFlags(&evFork, cudaEventDisableTiming);
        cudaEventCreateWithFlags(&evJoin, cudaEventDisableTiming);
        cudaEventCreateWithFlags(&evJoin3, cudaEventDisableTiming);
    }

    // ---- fork immediately ----------------------------------------------------------
    cudaEventRecord(evFork, 0);
    cudaStreamWaitEvent(s2, evFork, 0);
    cudaStreamWaitEvent(s3, evFork, 0);

    // s2: attention chain
    PrepackParams pa;
    for (int i = 0; i < 6; i++) {
        pa.d[i]     = {Wk + (size_t)i * 262144, Wk + (size_t)i * 262144, WKOFF + i * SMALL, 512};
        pa.d[6 + i] = {Wq + (size_t)i * 262144, Wq + (size_t)i * 262144, WQOFF + i * SMALL, 512};
    }
    prepack_all<<<dim3(16, 16, 12), dim3(32, 8), 0, s2>>>(pa);
    convert_att<<<dim3(1024, 4), 128, 0, s2>>>(kb_keys, query);
    gemm_tc<<<dim3(4, 1, 6), 256, 98304, s2>>>(
        qh, 0, 1, wbh + WQOFF, SMALL, 512,
        nullptr, nullptr, nullptr, 6,
        nullptr, 0, qb, nullptr, nullptr, nullptr, nullptr,
        nullptr, nullptr, nullptr, nullptr, nullptr, nullptr);
    gemm_tc<<<dim3(4, 32, 6), 256, 98304, s2>>>(
        atth, ATTZ, 3, wbh + WKOFF, SMALL, 512,
        nullptr, nullptr, nullptr, 3,
        nullptr, 0, qb, nullptr, nullptr, v_att, upart,
        nullptr, nullptr, nullptr, nullptr, nullptr, nullptr);
    detect_mask_kernel<<<1, 1024, 0, s2>>>((const unsigned int*)kb_mask);
    utk_kernel<<<dim3(KBTOT / 256, BSZ), 256, 0, s2>>>(upart, kb_mask, out_utk);
    cudaEventRecord(evJoin, s2);

    // s3: coalesced converters + eng, overlapping MLP prepack on main
    convert_info<<<8192, 256, 0, s3>>>(x, hidden, ah);
    eng_kernel<<<BT / 8, 256, 0, s3>>>(cell, eng_w, engp);
    cudaEventRecord(evJoin3, s3);

    // main: MLP weight prepack (10 slots)
    PrepackParams pm;
    pm.d[0] = {arn_w1, arn_w1 + 262144, W1OFF + 0 * BIG, 1024};
    pm.d[1] = {add_w1, add_w1 + 262144, W1OFF + 1 * BIG, 1024};
    pm.d[2] = {wc_w1,  wc_w1  + 262144, W1OFF + 2 * BIG, 1024};
    const float* sw[7] = {arn_w2, arn_w3, add_w2, add_w3, wc_w2, wc_w3, wc_w4};
    for (int j = 0; j < 7; j++)
        pm.d[3 + j] = {sw[j], sw[j], WSOFF2 + j * SMALL, 512};
    for (int j = 10; j < 12; j++) pm.d[j] = pm.d[9];
    prepack_all<<<dim3(32, 16, 10), dim3(32, 8)>>>(pm);
    cudaStreamWaitEvent(0, evJoin3, 0);

    // L1: info @ w1 -> h1 hi planes (relu)
    gemm_tc<<<dim3(4, 256, 3), 256, 98304>>>(
        ah, 0, 0, wbh + W1OFF, BIG, 1024,
        arn_b1, add_b1, wc_b1, 0,
        ah + H1_OFF, H1S, nullptr, nullptr, nullptr, nullptr, nullptr,
        nullptr, nullptr, nullptr, nullptr, nullptr, nullptr);
    // L2: h1 @ w2 -> h2 hi planes (relu)
    gemm_tc<<<dim3(4, 256, 3), 256, 98304>>>(
        ah + H1_OFF, H1S, 0, wbh + WSOFF2, 2 * SMALL, 512,
        arn_b2, add_b2, wc_b2, 0,
        ah + H2_OFF, H1S, nullptr, nullptr, nullptr, nullptr, nullptr,
        nullptr, nullptr, nullptr, nullptr, nullptr, nullptr);
    // L3: h2 @ w3; z0 sigmoid->arnh(fp16), z1 tanh->addh(fp16), z2 relu->h3 plane
    gemm_tc<<<dim3(4, 256, 3), 256, 98304>>>(
        ah + H2_OFF, H1S, 0, wbh + WSOFF2 + SMALL, 2 * SMALL, 512,
        arn_b3, add_b3, wc_b3, 5,
        ah + H1_OFF, 0, nullptr, arnh, addh, nullptr, nullptr,
        nullptr, nullptr, nullptr, nullptr, nullptr, nullptr);
    // L4: h3 @ wc_w4 -> fused final epilogue
    gemm_tc<<<dim3(4, 256, 1), 256, 98304>>>(
        ah + H1_OFF, 0, 0, wbh + WSOFF2 + 6 * SMALL, SMALL, 512,
        wc_b4, wc_b4, wc_b4, 4,
        nullptr, 0, nullptr, nullptr, nullptr, nullptr, nullptr,
        arnh, addh, cell, engp, outH, outC);

    // ---- join -----------------------------------------------------------------------
    cudaStreamWaitEvent(0, evJoin, 0);
}